// round 14
// baseline (speedup 1.0000x reference)
#include <cuda_runtime.h>

// ---------------- problem constants ----------------
#define G8      8
#define DK8     8
#define DV16    16
#define CIN64   64
#define H48     48
#define B2304   2304
#define P110592 110592      // B * H
#define NOUT    256         // 192 kv rows + 64 q rows
#define RELW    95          // 2K-1
#define EPS     1e-5f

typedef unsigned long long u64;

// ---- packed f32x2 helpers ----
__device__ __forceinline__ void fma2(u64& d, u64 a, u64 b) {
    asm("fma.rn.f32x2 %0, %1, %2, %0;" : "+l"(d) : "l"(a), "l"(b));
}
__device__ __forceinline__ u64 bcast2(float v) {
    u64 r; asm("mov.b64 %0, {%1, %1};" : "=l"(r) : "f"(v)); return r;
}
__device__ __forceinline__ float2 unpk2(u64 v) {
    float2 f; asm("mov.b64 {%0, %1}, %2;" : "=f"(f.x), "=f"(f.y) : "l"(v)); return f;
}

// ---------------- scratch (device globals; zero-initialized at load,
//                  re-zeroed by k_outco each call -> replay-invariant) ----
__device__ float  g_Q  [G8*DK8*H48*B2304];   // [(g*8+c)*48+h][b]  raw projection
__device__ float  g_Kb [G8*DK8*H48*B2304];
__device__ float  g_Vb [G8*DV16*H48*B2304];
__device__ float  g_SV [B2304*G8*DV16*H48];  // [b][(g*16+c)*48+i]
__device__ float  g_SVE[B2304*G8*DV16*H48];
__device__ double g_projstats[NOUT*2];
__device__ float  g_simco[G8*4];
__device__ double g_outstats[NOUT*2];
__device__ float  g_oA[NOUT], g_oC[NOUT];

__device__ float  g_SqTot[G8][8][48];
__device__ float  g_SkTot[G8][8][48];
__device__ float  g_PqTot[G8][36][48];
__device__ float  g_PkTot[G8][36][48];
__device__ double g_qkstat[G8][2];

__device__ __forceinline__ void pair_cc(int p, int& c, int& c2) {
    int base = 0, cc = 0;
#pragma unroll
    for (int r = 0; r < 8; r++) {
        int cnt = 8 - r;
        if (p < base + cnt) { cc = r; break; }
        base += cnt;
    }
    c = cc; c2 = cc + (p - base);
}

__device__ __forceinline__ void chan_affine(int o, float gg, float bb,
                                            float& a, float& sh) {
    double s1 = g_projstats[2*o], s2 = g_projstats[2*o+1];
    double mean = s1 / (double)P110592;
    double var  = s2 / (double)P110592 - mean * mean;
    float inv = rsqrtf((float)var + EPS);
    a  = gg * inv;
    sh = bb - a * (float)mean;
}

// ---------------- projection GEMM: packed-f32x2 mainloop ----------------
#define PJ_SMEM ((64*128 + 64*132 + 256) * 4)
__global__ __launch_bounds__(256, 2)
void k_proj(const float* __restrict__ x,
            const float* __restrict__ Wkv,
            const float* __restrict__ Wq) {
    extern __shared__ float sm[];
    float* Xs = sm;                // [64][128]
    float* Ws = Xs + 64*128;       // [64][132]
    float* ss = Ws + 64*132;       // [128][2] block stats

    int tid = threadIdx.x;
    int ts = tid & 15, to = tid >> 4;
    int og = blockIdx.y;
    int s0 = blockIdx.x * 128;
    int h  = s0 / B2304;
    int bb = s0 - h * B2304;

    if (tid < 256) ss[tid] = 0.f;

#pragma unroll
    for (int it = 0; it < 8; it++) {
        int i = tid + it * 256;
        int c = i >> 5, q = i & 31;
        float4 v = *(const float4*)(x + c * P110592 + s0 + q * 4);
        *(float4*)(&Xs[c * 128 + q * 4]) = v;
    }
#pragma unroll
    for (int it = 0; it < 8; it++) {
        int i = tid + it * 256;
        int o_l = i >> 4, q = i & 15;
        int o = og * 128 + o_l;
        float4 w = (o < 192) ? *(const float4*)(Wkv + o * 64 + q * 4)
                             : *(const float4*)(Wq + (o - 192) * 64 + q * 4);
        int k0 = q * 4;
        Ws[(k0 + 0) * 132 + o_l] = w.x;
        Ws[(k0 + 1) * 132 + o_l] = w.y;
        Ws[(k0 + 2) * 132 + o_l] = w.z;
        Ws[(k0 + 3) * 132 + o_l] = w.w;
    }
    __syncthreads();

    u64 acc2[8][4];
#pragma unroll
    for (int a = 0; a < 8; a++)
#pragma unroll
        for (int b = 0; b < 4; b++) acc2[a][b] = 0ull;

#pragma unroll 4
    for (int k = 0; k < 64; k++) {
        ulonglong2 xa = *(ulonglong2*)(&Xs[k * 128 + ts * 8]);
        ulonglong2 xb = *(ulonglong2*)(&Xs[k * 128 + ts * 8 + 4]);
        u64 px[4] = {xa.x, xa.y, xb.x, xb.y};
        float4 wa = *(float4*)(&Ws[k * 132 + to * 8]);
        float4 wb = *(float4*)(&Ws[k * 132 + to * 8 + 4]);
        float wf[8] = {wa.x, wa.y, wa.z, wa.w, wb.x, wb.y, wb.z, wb.w};
#pragma unroll
        for (int oo = 0; oo < 8; oo++) {
            u64 w2 = bcast2(wf[oo]);
#pragma unroll
            for (int i = 0; i < 4; i++)
                fma2(acc2[oo][i], w2, px[i]);
        }
    }

    float acc[8][8];
#pragma unroll
    for (int oo = 0; oo < 8; oo++)
#pragma unroll
        for (int i = 0; i < 4; i++) {
            float2 f = unpk2(acc2[oo][i]);
            acc[oo][2*i] = f.x; acc[oo][2*i+1] = f.y;
        }

#pragma unroll
    for (int oo = 0; oo < 8; oo++) {
        int o = og * 128 + to * 8 + oo;
        float* dst;
        if (o < 192) {
            int g = o / 24, cc = o - g * 24;
            if (cc < 8) dst = &g_Kb[((g*8 + cc)      * H48 + h) * B2304];
            else        dst = &g_Vb[((g*16 + (cc-8)) * H48 + h) * B2304];
        } else {
            dst = &g_Q[((o - 192) * H48 + h) * B2304];
        }
        float4 v0 = make_float4(acc[oo][0], acc[oo][1], acc[oo][2], acc[oo][3]);
        float4 v1 = make_float4(acc[oo][4], acc[oo][5], acc[oo][6], acc[oo][7]);
        *(float4*)(dst + bb + ts * 8)     = v0;
        *(float4*)(dst + bb + ts * 8 + 4) = v1;

        float s1 = 0.f, s2 = 0.f;
#pragma unroll
        for (int i = 0; i < 8; i++) { s1 += acc[oo][i]; s2 = fmaf(acc[oo][i], acc[oo][i], s2); }
#pragma unroll
        for (int off = 1; off < 16; off <<= 1) {
            s1 += __shfl_xor_sync(0xffffffffu, s1, off);
            s2 += __shfl_xor_sync(0xffffffffu, s2, off);
        }
        if (ts == 0) {
            atomicAdd(&ss[(to * 8 + oo) * 2],     s1);
            atomicAdd(&ss[(to * 8 + oo) * 2 + 1], s2);
        }
    }
    __syncthreads();
    if (tid < 128) {
        int o = og * 128 + tid;
        atomicAdd(&g_projstats[2*o],   (double)ss[tid*2]);
        atomicAdd(&g_projstats[2*o+1], (double)ss[tid*2+1]);
    }
}

// ---------------- statsAB: merged per-position moments (A) + qk Grams (B) ----------------
__global__ __launch_bounds__(256)
void k_statsAB(const float* __restrict__ gkv, const float* __restrict__ bkv,
               const float* __restrict__ gq,  const float* __restrict__ bq) {
    __shared__ float red[8][88];
    __shared__ float tot[88];
    __shared__ float paq[8], pbq[8], pak[8], pbk[8];

    int tid = threadIdx.x;
    int g   = blockIdx.y;

    if (tid < 16) {
        int c = tid & 7;
        bool isq = tid < 8;
        int o = isq ? (192 + g*8 + c) : (g*24 + c);
        float gg = isq ? gq[g*8 + c] : gkv[o];
        float bb = isq ? bq[g*8 + c] : bkv[o];
        float a, sh; chan_affine(o, gg, bb, a, sh);
        if (isq) { paq[c] = a; pbq[c] = sh; }
        else     { pak[c] = a; pbk[c] = sh; }
    }
    __syncthreads();

    if (blockIdx.x < 48) {
        int i = blockIdx.x;
        const float* Qb = g_Q  + (g*384 + i) * B2304;
        const float* Kb = g_Kb + (g*384 + i) * B2304;

        float A[88];
#pragma unroll
        for (int t = 0; t < 88; t++) A[t] = 0.f;

#pragma unroll 3
        for (int ch = 0; ch < 9; ch++) {
            int b = tid + ch * 256;
            float qv[8], kv[8];
#pragma unroll
            for (int c = 0; c < 8; c++) qv[c] = Qb[c * (48*B2304) + b];
#pragma unroll
            for (int c = 0; c < 8; c++) kv[c] = Kb[c * (48*B2304) + b];
#pragma unroll
            for (int c = 0; c < 8; c++) { A[c] += qv[c]; A[44 + c] += kv[c]; }
            int p = 0;
#pragma unroll
            for (int c = 0; c < 8; c++)
#pragma unroll
                for (int c2 = c; c2 < 8; c2++) {
                    A[8 + p]  = fmaf(qv[c], qv[c2], A[8 + p]);
                    A[52 + p] = fmaf(kv[c], kv[c2], A[52 + p]);
                    p++;
                }
        }

        int lane = tid & 31, w = tid >> 5;
#pragma unroll
        for (int t = 0; t < 88; t++) {
            float v = A[t];
            v += __shfl_xor_sync(0xffffffffu, v, 16);
            v += __shfl_xor_sync(0xffffffffu, v, 8);
            v += __shfl_xor_sync(0xffffffffu, v, 4);
            v += __shfl_xor_sync(0xffffffffu, v, 2);
            v += __shfl_xor_sync(0xffffffffu, v, 1);
            if (lane == 0) red[w][t] = v;
        }
        __syncthreads();
        if (tid < 88) {
            float s = 0.f;
#pragma unroll
            for (int ww = 0; ww < 8; ww++) s += red[ww][tid];
            tot[tid] = s;
        }
        __syncthreads();
        if (tid < 88) {
            float s = tot[tid];
            const float N = (float)B2304;
            if (tid < 8) {
                int c = tid;
                g_SqTot[g][c][i] = paq[c] * s + N * pbq[c];
            } else if (tid < 44) {
                int p = tid - 8, c, c2; pair_cc(p, c, c2);
                float a1 = paq[c], b1 = pbq[c], a2 = paq[c2], b2 = pbq[c2];
                g_PqTot[g][p][i] = a1*a2*s + a1*b2*tot[c] + a2*b1*tot[c2] + N*b1*b2;
            } else if (tid < 52) {
                int c = tid - 44;
                g_SkTot[g][c][i] = pak[c] * s + N * pbk[c];
            } else {
                int p = tid - 52, c, c2; pair_cc(p, c, c2);
                float a1 = pak[c], b1 = pbk[c], a2 = pak[c2], b2 = pbk[c2];
                g_PkTot[g][p][i] = a1*a2*s + a1*b2*tot[44 + c] + a2*b1*tot[44 + c2] + N*b1*b2;
            }
        }
    } else {
        int b = (blockIdx.x - 48) * 256 + tid;
        const float* Qb = g_Q  + (g*384) * B2304 + b;
        const float* Kb = g_Kb + (g*384) * B2304 + b;

        float A[88];
#pragma unroll
        for (int t = 0; t < 88; t++) A[t] = 0.f;

#pragma unroll 2
        for (int i = 0; i < 48; i++) {
            float qv[8], kv[8];
#pragma unroll
            for (int c = 0; c < 8; c++) qv[c] = Qb[(c*48 + i) * B2304];
#pragma unroll
            for (int c = 0; c < 8; c++) kv[c] = Kb[(c*48 + i) * B2304];
#pragma unroll
            for (int c = 0; c < 8; c++) { A[c] += qv[c]; A[44 + c] += kv[c]; }
            int p = 0;
#pragma unroll
            for (int c = 0; c < 8; c++)
#pragma unroll
                for (int c2 = c; c2 < 8; c2++) {
                    A[8 + p]  = fmaf(qv[c], qv[c2], A[8 + p]);
                    A[52 + p] = fmaf(kv[c], kv[c2], A[52 + p]);
                    p++;
                }
        }

        float Rq[8], Rk[8];
#pragma unroll
        for (int c = 0; c < 8; c++) {
            Rq[c] = fmaf(paq[c], A[c],      48.f * pbq[c]);
            Rk[c] = fmaf(pak[c], A[44 + c], 48.f * pbk[c]);
        }
        float s1 = 0.f;
#pragma unroll
        for (int c = 0; c < 8; c++) s1 = fmaf(Rq[c], Rk[c], s1);

        float s2 = 0.f;
        {
            int p = 0;
#pragma unroll
            for (int c = 0; c < 8; c++)
#pragma unroll
                for (int c2 = c; c2 < 8; c2++) {
                    float Gq = paq[c]*paq[c2]*A[8 + p]  + paq[c]*pbq[c2]*A[c]
                             + paq[c2]*pbq[c]*A[c2]     + 48.f*pbq[c]*pbq[c2];
                    float Gk = pak[c]*pak[c2]*A[52 + p] + pak[c]*pbk[c2]*A[44 + c]
                             + pak[c2]*pbk[c]*A[44 + c2] + 48.f*pbk[c]*pbk[c2];
                    float w = (c == c2) ? 1.f : 2.f;
                    s2 = fmaf(w * Gq, Gk, s2);
                    p++;
                }
        }

        double d1 = (double)s1, d2 = (double)s2;
#pragma unroll
        for (int off = 16; off; off >>= 1) {
            d1 += __shfl_xor_sync(0xffffffffu, d1, off);
            d2 += __shfl_xor_sync(0xffffffffu, d2, off);
        }
        if ((tid & 31) == 0) {
            atomicAdd(&g_qkstat[g][0], d1);
            atomicAdd(&g_qkstat[g][1], d2);
        }
    }
}

// ---------------- finalize sim BN coefficients ----------------
__global__ __launch_bounds__(256)
void k_simfin(const float* __restrict__ rel,
              const float* __restrict__ gsim, const float* __restrict__ bsim,
              const float* __restrict__ fqr,  const float* __restrict__ fkr) {
    __shared__ float relq_s[8*RELW], relk_s[8*RELW];
    __shared__ float Rq[384], Rk[384];
    __shared__ float ERq[1728], ERk[1728];
    __shared__ double warp_out[8][4];

    int tid = threadIdx.x;
    for (int i = tid; i < 16*RELW; i += 256) {
        if (i < 8*RELW) relq_s[i] = rel[i];
        else            relk_s[i - 8*RELW] = rel[i];
    }
    __syncthreads();

    for (int it = tid; it < 384; it += 256) {
        int c = it / 48, i = it - (it/48)*48;
        float s = 0.f, sk = 0.f;
#pragma unroll 8
        for (int d = 0; d < 48; d++) {
            s  += relq_s[c*RELW + i + d];
            sk += relk_s[c*RELW + i + d];
        }
        Rq[it] = s; Rk[it] = sk;
    }
    for (int it = tid; it < 1728; it += 256) {
        int p = it / 48, i = it - (it/48)*48;
        int c, c2; pair_cc(p, c, c2);
        float s = 0.f, sk = 0.f;
#pragma unroll 8
        for (int d = 0; d < 48; d++) {
            s  = fmaf(relq_s[c*RELW + i + d], relq_s[c2*RELW + i + d], s);
            sk = fmaf(relk_s[c*RELW + i + d], relk_s[c2*RELW + i + d], sk);
        }
        ERq[it] = s; ERk[it] = sk;
    }
    __syncthreads();

    int w = tid >> 5, lane = tid & 31;
    int g = w;
    double qr_s = 0.0, qr_q = 0.0, kr_s = 0.0, kr_q = 0.0;
    for (int it = lane; it < 384; it += 32) {
        int c = it / 48, i = it - (it/48)*48;
        qr_s += (double)g_SqTot[g][c][i] * (double)Rq[it];
        kr_s += (double)g_SkTot[g][c][i] * (double)Rk[it];
    }
    for (int it = lane; it < 1728; it += 32) {
        int p = it / 48, i = it - (it/48)*48;
        int c, c2; pair_cc(p, c, c2);
        double ww = (c == c2) ? 1.0 : 2.0;
        qr_q += ww * (double)g_PqTot[g][p][i] * (double)ERq[it];
        kr_q += ww * (double)g_PkTot[g][p][i] * (double)ERk[it];
    }
#pragma unroll
    for (int off = 16; off; off >>= 1) {
        qr_s += __shfl_xor_sync(0xffffffffu, qr_s, off);
        qr_q += __shfl_xor_sync(0xffffffffu, qr_q, off);
        kr_s += __shfl_xor_sync(0xffffffffu, kr_s, off);
        kr_q += __shfl_xor_sync(0xffffffffu, kr_q, off);
    }
    if (lane == 0) {
        warp_out[w][0] = qr_s; warp_out[w][1] = qr_q;
        warp_out[w][2] = kr_s; warp_out[w][3] = kr_q;
    }
    __syncthreads();
    if (tid < 8) {
        int gg = tid;
        double N = (double)B2304 * 48.0 * 48.0;
        double fq = (double)(*fqr), fk = (double)(*fkr);

        double m0 = g_qkstat[gg][0] / N;
        double v0 = g_qkstat[gg][1] / N - m0 * m0;
        double m1 = fq * warp_out[gg][0] / N;
        double v1 = fq * fq * warp_out[gg][1] / N - m1 * m1;
        double m2 = fk * warp_out[gg][2] / N;
        double v2 = fk * fk * warp_out[gg][3] / N - m2 * m2;

        double i0 = 1.0 / sqrt(v0 + (double)EPS);
        double i1 = 1.0 / sqrt(v1 + (double)EPS);
        double i2 = 1.0 / sqrt(v2 + (double)EPS);

        double a0 = (double)gsim[0*G8 + gg] * i0;
        double a1 = (double)gsim[1*G8 + gg] * i1;
        double a2 = (double)gsim[2*G8 + gg] * i2;
        double shift = (double)bsim[0*G8+gg] - a0*m0
                     + (double)bsim[1*G8+gg] - a1*m1
                     + (double)bsim[2*G8+gg] - a2*m2;
        g_simco[gg*4+0] = (float)a0;
        g_simco[gg*4+1] = (float)(a1 * fq);
        g_simco[gg*4+2] = (float)(a2 * fk);
        g_simco[gg*4+3] = (float)shift;
    }
}

// ---------------- attention: BTL=4, all-sims then all-sv (amortized rv/sim traffic) ----
#define BTL 4
// Qs 1536 + Ks 1536 + Vs 3072 + sim 4*2352=9408 + rq 760 + rk 760 + rv 1520 = 18592 floats
#define AT_SMEM (18592 * 4)
__global__ __launch_bounds__(256, 2)
void k_attn(const float* __restrict__ rel,
            const float* __restrict__ fsv, const float* __restrict__ fsve,
            const float* __restrict__ gkv, const float* __restrict__ bkv,
            const float* __restrict__ gq,  const float* __restrict__ bq) {
    extern __shared__ float sm[];
    float* Qs   = sm;                    // [bl][i][8]  (pre-scaled by A0)
    float* Ks   = Qs + BTL*48*8;         // [bl][j][8]
    float* Vs   = Ks + BTL*48*8;         // [bl][j][16] (f_sv folded)
    float* simA = Vs + BTL*48*16;        // [bl][48][49]
    float* rq_t = simA + BTL*48*49;      // [d][8]   (pre-scaled by A1/A0)
    float* rk_t = rq_t + RELW*8;         // [d][8]   (pre-scaled by A2)
    float* rv_t = rk_t + RELW*8;         // [d][16]  (pre-scaled by f_sve)
    __shared__ double red[64];
    __shared__ float pa_s[32], pb_s[32]; // 0-7 q, 8-15 k, 16-31 v

    int tid = threadIdx.x;
    int g   = blockIdx.y;
    int b0  = blockIdx.x * BTL;

    float A0 = g_simco[g*4+0], A1 = g_simco[g*4+1];
    float A2 = g_simco[g*4+2], SH = g_simco[g*4+3];
    float A1oA0 = A1 / A0;
    float vsv = *fsv, vsve = *fsve;

    if (tid < 32) {
        int o; float gg, bb;
        if (tid < 8)       { o = 192 + g*8 + tid;   gg = gq[g*8 + tid];  bb = bq[g*8 + tid]; }
        else if (tid < 16) { o = g*24 + (tid - 8);  gg = gkv[o];         bb = bkv[o]; }
        else               { o = g*24 + 8 + (tid - 16); gg = gkv[o];     bb = bkv[o]; }
        float a, sh; chan_affine(o, gg, bb, a, sh);
        pa_s[tid] = a; pb_s[tid] = sh;
    }
    __syncthreads();

    for (int i = tid; i < RELW*8; i += 256) {
        int d = i >> 3, c = i & 7;
        rq_t[i] = rel[c*RELW + d] * A1oA0;
        rk_t[i] = rel[(8 + c)*RELW + d] * A2;
    }
    for (int i = tid; i < RELW*16; i += 256) {
        int d = i >> 4, c = i & 15;
        rv_t[i] = rel[(16 + c)*RELW + d] * vsve;
    }
    // Q/K staging: 384 rows, one float4 (4 b's) each
    for (int row = tid; row < 384; row += 256) {
        int c = row / 48, i = row % 48;
        float4 vq = *(const float4*)(&g_Q [(g*384 + row) * B2304 + b0]);
        float4 vk = *(const float4*)(&g_Kb[(g*384 + row) * B2304 + b0]);
        float aq = pa_s[c] * A0, bqv = pb_s[c] * A0;   // fold A0 into Q
        float ak = pa_s[8 + c], bkv2 = pb_s[8 + c];
        float qv[4] = {vq.x, vq.y, vq.z, vq.w};
        float kv[4] = {vk.x, vk.y, vk.z, vk.w};
#pragma unroll
        for (int e = 0; e < 4; e++) {
            Qs[e*384 + i*8 + c] = fmaf(aq, qv[e], bqv);
            Ks[e*384 + i*8 + c] = fmaf(ak, kv[e], bkv2);
        }
    }
    // V staging: 768 rows
    for (int row = tid; row < 768; row += 256) {
        int c = row / 48, j = row % 48;
        float4 vv = *(const float4*)(&g_Vb[(g*768 + row) * B2304 + b0]);
        float av = pa_s[16 + c] * vsv, bv = pb_s[16 + c] * vsv;
        float vf[4] = {vv.x, vv.y, vv.z, vv.w};
#pragma unroll
        for (int e = 0; e < 4; e++)
            Vs[e*768 + j*16 + c] = fmaf(av, vf[e], bv);
    }
    for (int i = tid; i < 64; i += 256) red[i] = 0.0;
    __syncthreads();

    int ti = tid >> 4, tj = tid & 15;
    int i0 = ti * 3, j0 = tj * 3;
    int D0 = i0 - j0 + 45;     // rq rows D0..D0+4 (dd = r-s+2)
    int D2 = j0 - i0 + 45;     // rk rows D2..D2+4 (dd = s-r+2)

    // ---- logits + softmax for all 4 bl ----
#pragma unroll
    for (int bl = 0; bl < BTL; bl++) {
        const float* Q = Qs + bl*384;
        const float* K = Ks + bl*384;
        float* sim = simA + bl*2352;

        u64 q2[3][4], k2[3][4];
#pragma unroll
        for (int r = 0; r < 3; r++) {
            ulonglong2 a = *(const ulonglong2*)(&Q[(i0 + r)*8]);
            ulonglong2 b = *(const ulonglong2*)(&Q[(i0 + r)*8 + 4]);
            q2[r][0] = a.x; q2[r][1] = a.y; q2[r][2] = b.x; q2[r][3] = b.y;
        }
#pragma unroll
        for (int s = 0; s < 3; s++) {
            ulonglong2 a = *(const ulonglong2*)(&K[(j0 + s)*8]);
            ulonglong2 b = *(const ulonglong2*)(&K[(j0 + s)*8 + 4]);
            k2[s][0] = a.x; k2[s][1] = a.y; k2[s][2] = b.x; k2[s][3] = b.y;
        }
        u64 acc[3][3];
#pragma unroll
        for (int r = 0; r < 3; r++)
#pragma unroll
            for (int s = 0; s < 3; s++) acc[r][s] = 0ull;
#pragma unroll
        for (int cp = 0; cp < 4; cp++)
#pragma unroll
            for (int r = 0; r < 3; r++)
#pragma unroll
                for (int s = 0; s < 3; s++)
                    fma2(acc[r][s], q2[r][cp], k2[s][cp]);
        // rel terms: 5-row dd structure (qr into acc via A1/A0 pre-scale; kr via A2)
#pragma unroll
        for (int dd = 0; dd < 5; dd++) {
            {
                const float* rr = &rq_t[(D0 + dd)*8];
                ulonglong2 a = *(const ulonglong2*)(rr);
                ulonglong2 b = *(const ulonglong2*)(rr + 4);
                u64 rq[4] = {a.x, a.y, b.x, b.y};
#pragma unroll
                for (int r = 0; r < 3; r++)
#pragma unroll
                    for (int s = 0; s < 3; s++)
                        if (r - s + 2 == dd)
#pragma unroll
                            for (int cp = 0; cp < 4; cp++)
                                fma2(acc[r][s], q2[r][cp], rq[cp]);
            }
            {
                const float* rr = &rk_t[(D2 + dd)*8];
                ulonglong2 a = *(const ulonglong2*)(rr);
                ulonglong2 b = *(const ulonglong2*)(rr + 4);
                u64 rk[4] = {a.x, a.y, b.x, b.y};
#pragma unroll
                for (int r = 0; r < 3; r++)
#pragma unroll
                    for (int s = 0; s < 3; s++)
                        if (s - r + 2 == dd)
#pragma unroll
                            for (int cp = 0; cp < 4; cp++)
                                fma2(acc[r][s], k2[s][cp], rk[cp]);
            }
        }
        // exp + fused row softmax (BN-normalized logits; no max-sub needed)
        float e[3][3], rs[3];
#pragma unroll
        for (int r = 0; r < 3; r++) {
            rs[r] = 0.f;
#pragma unroll
            for (int s = 0; s < 3; s++) {
                float2 aa = unpk2(acc[r][s]);
                e[r][s] = __expf(aa.x + aa.y + SH);
                rs[r] += e[r][s];
            }
        }
#pragma unroll
        for (int off = 1; off < 16; off <<= 1) {
#pragma unroll
            for (int r = 0; r < 3; r++)
                rs[r] += __shfl_xor_sync(0xffffffffu, rs[r], off);
        }
#pragma unroll
        for (int r = 0; r < 3; r++) {
            float rinv = 1.f / rs[r];
#pragma unroll
            for (int s = 0; s < 3; s++)
                sim[(i0 + r)*49 + j0 + s] = e[r][s] * rinv;
        }
    }
    __syncthreads();   // one barrier for all 4 sims

    // ---- sv / sve for all 4 bl: rv read once serves 4 bl ----
    int sv_i  = tid >> 2;
    int sv_c0 = (tid & 3) * 4;

    float lsv_s[4]  = {0,0,0,0}, lsv_q[4]  = {0,0,0,0};
    float lsve_s[4] = {0,0,0,0}, lsve_q[4] = {0,0,0,0};

    if (tid < 192) {
        u64 sv2[BTL][2], se2[BTL][2];
#pragma unroll
        for (int bl = 0; bl < BTL; bl++) {
            sv2[bl][0] = 0ull; sv2[bl][1] = 0ull;
            se2[bl][0] = 0ull; se2[bl][1] = 0ull;
        }
#pragma unroll 2
        for (int j = 0; j < 48; j++) {
            ulonglong2 rv = *(const ulonglong2*)(&rv_t[(sv_i - j + 47)*16 + sv_c0]);
            int sidx = sv_i*49 + j;
#pragma unroll
            for (int bl = 0; bl < BTL; bl++) {
                float s = simA[bl*2352 + sidx];
                u64 s2 = bcast2(s);
                ulonglong2 v = *(const ulonglong2*)(&Vs[bl*768 + j*16 + sv_c0]);
                fma2(sv2[bl][0], s2, v.x);  fma2(sv2[bl][1], s2, v.y);
                fma2(se2[bl][0], s2, rv.x); fma2(se2[bl][1], s2, rv.y);
            }
        }
#pragma unroll
        for (int bl = 0; bl < BTL; bl++) {
            int b = b0 + bl;
            float* outv = &g_SV [b*6144 + g*768 + sv_c0*48 + sv_i];
            float* oute = &g_SVE[b*6144 + g*768 + sv_c0*48 + sv_i];
            float2 f0 = unpk2(sv2[bl][0]), f1 = unpk2(sv2[bl][1]);
            float2 g0 = unpk2(se2[bl][0]), g1 = unpk2(se2[bl][1]);
            float svv[4] = {f0.x, f0.y, f1.x, f1.y};
            float sev[4] = {g0.x, g0.y, g1.x, g1.y};
#pragma unroll
            for (int cc = 0; cc < 4; cc++) {
                outv[cc*48] = svv[cc];
                oute[cc*48] = sev[cc];
                lsv_s[cc]  += svv[cc]; lsv_q[cc]  += svv[cc]*svv[cc];
                lsve_s[cc] += sev[cc]; lsve_q[cc] += sev[cc]*sev[cc];
            }
        }
#pragma unroll
        for (int cc = 0; cc < 4; cc++) {
            int c = sv_c0 + cc;
            atomicAdd(&red[c*4+0], (double)lsv_s[cc]);
            atomicAdd(&red[c*4+1], (double)lsv_q[cc]);
            atomicAdd(&red[c*4+2], (double)lsve_s[cc]);
            atomicAdd(&red[c*4+3], (double)lsve_q[cc]);
        }
    }
    __syncthreads();
    if (tid < 16) {
        int o_sv  = (g*16 + tid)*2;
        int o_sve = o_sv + 1;
        atomicAdd(&g_outstats[o_sv*2+0],  red[tid*4+0]);
        atomicAdd(&g_outstats[o_sv*2+1],  red[tid*4+1]);
        atomicAdd(&g_outstats[o_sve*2+0], red[tid*4+2]);
        atomicAdd(&g_outstats[o_sve*2+1], red[tid*4+3]);
    }
}

// ---------------- out BN coefficients + restore accumulators to zero ----------------
__global__ void k_outco(const float* __restrict__ gout, const float* __restrict__ bout) {
    int o = threadIdx.x;
    double N = (double)P110592;
    double s1 = g_outstats[2*o], s2 = g_outstats[2*o+1];
    double mean = s1 / N, var = s2 / N - mean * mean;
    float inv = rsqrtf((float)var + EPS);
    float A = gout[o] * inv;
    g_oA[o] = A;
    g_oC[o] = bout[o] - A * (float)mean;
    g_outstats[2*o] = 0.0;  g_outstats[2*o+1] = 0.0;
    g_projstats[2*o] = 0.0; g_projstats[2*o+1] = 0.0;
    if (o < G8*2) ((double*)g_qkstat)[o] = 0.0;
}

// ---------------- final: affine-combine + transpose [b][r] -> [r][b] ----------------
__global__ __launch_bounds__(256)
void k_final(float* __restrict__ out) {
    __shared__ float tile[32][33];
    int r0 = blockIdx.x * 32;
    int b0 = blockIdx.y * 32;
    int tx = threadIdx.x, ty = threadIdx.y;

    int r = r0 + tx;
    int gc = r / 48;
    float Asv  = g_oA[gc*2],   Csv  = g_oC[gc*2];
    float Asve = g_oA[gc*2+1], Csve = g_oC[gc*2+1];
#pragma unroll
    for (int k = 0; k < 4; k++) {
        int b = b0 + ty + k*8;
        float v = Asv * g_SV[b*6144 + r] + Csv
                + Asve * g_SVE[b*6144 + r] + Csve;
        tile[ty + k*8][tx] = v;
    }
    __syncthreads();
#pragma unroll
    for (int k = 0; k < 4; k++) {
        int rr = r0 + ty + k*8;
        out[rr * B2304 + b0 + tx] = tile[tx][ty + k*8];
    }
}

// ---------------- launch ----------------
extern "C" void kernel_launch(void* const* d_in, const int* in_sizes, int n_in,
                              void* d_out, int out_size) {
    const float* x    = (const float*)d_in[0];
    const float* Wkv  = (const float*)d_in[1];
    const float* Wq   = (const float*)d_in[2];
    const float* gkv  = (const float*)d_in[3];
    const float* bkv  = (const float*)d_in[4];
    const float* gq   = (const float*)d_in[5];
    const float* bq   = (const float*)d_in[6];
    const float* gsim = (const float*)d_in[7];
    const float* bsim = (const float*)d_in[8];
    const float* gout = (const float*)d_in[9];
    const float* bout = (const float*)d_in[10];
    const float* rel  = (const float*)d_in[11];
    const float* fqr  = (const float*)d_in[12];
    const float* fkr  = (const float*)d_in[13];
    const float* fsv  = (const float*)d_in[14];
    const float* fsve = (const float*)d_in[15];
    float* out = (float*)d_out;

    cudaFuncSetAttribute(k_proj, cudaFuncAttributeMaxDynamicSharedMemorySize, PJ_SMEM);
    cudaFuncSetAttribute(k_attn, cudaFuncAttributeMaxDynamicSharedMemorySize, AT_SMEM);

    k_proj<<<dim3(P110592/128, 2), 256, PJ_SMEM>>>(x, Wkv, Wq);
    k_statsAB<<<dim3(48 + B2304/256, G8), 256>>>(gkv, bkv, gq, bq);
    k_simfin<<<1, 256>>>(rel, gsim, bsim, fqr, fkr);
    k_attn<<<dim3(B2304/BTL, G8), 256, AT_SMEM>>>(rel, fsv, fsve, gkv, bkv, gq, bq);
    k_outco<<<1, 256>>>(gout, bout);
    k_final<<<dim3(6144/32, B2304/32), dim3(32, 8)>>>(out);
}

// round 15
// speedup vs baseline: 1.2879x; 1.2879x over previous
#include <cuda_runtime.h>

// ---------------- problem constants ----------------
#define G8      8
#define DK8     8
#define DV16    16
#define CIN64   64
#define H48     48
#define B2304   2304
#define P110592 110592      // B * H
#define NOUT    256         // 192 kv rows + 64 q rows
#define RELW    95          // 2K-1
#define EPS     1e-5f

typedef unsigned long long u64;

// ---- packed f32x2 helpers ----
__device__ __forceinline__ void fma2(u64& d, u64 a, u64 b) {
    asm("fma.rn.f32x2 %0, %1, %2, %0;" : "+l"(d) : "l"(a), "l"(b));
}
__device__ __forceinline__ u64 bcast2(float v) {
    u64 r; asm("mov.b64 %0, {%1, %1};" : "=l"(r) : "f"(v)); return r;
}
__device__ __forceinline__ float2 unpk2(u64 v) {
    float2 f; asm("mov.b64 {%0, %1}, %2;" : "=f"(f.x), "=f"(f.y) : "l"(v)); return f;
}

// ---------------- scratch (device globals; zero-initialized at load,
//                  re-zeroed by k_outco each call -> replay-invariant) ----
__device__ float  g_Q  [G8*DK8*H48*B2304];   // [(g*8+c)*48+h][b]  raw projection
__device__ float  g_Kb [G8*DK8*H48*B2304];
__device__ float  g_Vb [G8*DV16*H48*B2304];
__device__ float  g_SV [B2304*G8*DV16*H48];  // [b][(g*16+c)*48+i]
__device__ float  g_SVE[B2304*G8*DV16*H48];
__device__ double g_projstats[NOUT*2];
__device__ float  g_simco[G8*4];
__device__ double g_outstats[NOUT*2];
__device__ float  g_oA[NOUT], g_oC[NOUT];

__device__ float  g_SqTot[G8][8][48];
__device__ float  g_SkTot[G8][8][48];
__device__ float  g_PqTot[G8][36][48];
__device__ float  g_PkTot[G8][36][48];
__device__ double g_qkstat[G8][2];

__device__ __forceinline__ void pair_cc(int p, int& c, int& c2) {
    int base = 0, cc = 0;
#pragma unroll
    for (int r = 0; r < 8; r++) {
        int cnt = 8 - r;
        if (p < base + cnt) { cc = r; break; }
        base += cnt;
    }
    c = cc; c2 = cc + (p - base);
}

__device__ __forceinline__ void chan_affine(int o, float gg, float bb,
                                            float& a, float& sh) {
    double s1 = g_projstats[2*o], s2 = g_projstats[2*o+1];
    double mean = s1 / (double)P110592;
    double var  = s2 / (double)P110592 - mean * mean;
    float inv = rsqrtf((float)var + EPS);
    a  = gg * inv;
    sh = bb - a * (float)mean;
}

// ---------------- projection GEMM: packed-f32x2 mainloop ----------------
#define PJ_SMEM ((64*128 + 64*132 + 256) * 4)
__global__ __launch_bounds__(256, 2)
void k_proj(const float* __restrict__ x,
            const float* __restrict__ Wkv,
            const float* __restrict__ Wq) {
    extern __shared__ float sm[];
    float* Xs = sm;                // [64][128]
    float* Ws = Xs + 64*128;       // [64][132]
    float* ss = Ws + 64*132;       // [128][2] block stats

    int tid = threadIdx.x;
    int ts = tid & 15, to = tid >> 4;
    int og = blockIdx.y;
    int s0 = blockIdx.x * 128;
    int h  = s0 / B2304;
    int bb = s0 - h * B2304;

    if (tid < 256) ss[tid] = 0.f;

#pragma unroll
    for (int it = 0; it < 8; it++) {
        int i = tid + it * 256;
        int c = i >> 5, q = i & 31;
        float4 v = *(const float4*)(x + c * P110592 + s0 + q * 4);
        *(float4*)(&Xs[c * 128 + q * 4]) = v;
    }
#pragma unroll
    for (int it = 0; it < 8; it++) {
        int i = tid + it * 256;
        int o_l = i >> 4, q = i & 15;
        int o = og * 128 + o_l;
        float4 w = (o < 192) ? *(const float4*)(Wkv + o * 64 + q * 4)
                             : *(const float4*)(Wq + (o - 192) * 64 + q * 4);
        int k0 = q * 4;
        Ws[(k0 + 0) * 132 + o_l] = w.x;
        Ws[(k0 + 1) * 132 + o_l] = w.y;
        Ws[(k0 + 2) * 132 + o_l] = w.z;
        Ws[(k0 + 3) * 132 + o_l] = w.w;
    }
    __syncthreads();

    u64 acc2[8][4];
#pragma unroll
    for (int a = 0; a < 8; a++)
#pragma unroll
        for (int b = 0; b < 4; b++) acc2[a][b] = 0ull;

#pragma unroll 4
    for (int k = 0; k < 64; k++) {
        ulonglong2 xa = *(ulonglong2*)(&Xs[k * 128 + ts * 8]);
        ulonglong2 xb = *(ulonglong2*)(&Xs[k * 128 + ts * 8 + 4]);
        u64 px[4] = {xa.x, xa.y, xb.x, xb.y};
        float4 wa = *(float4*)(&Ws[k * 132 + to * 8]);
        float4 wb = *(float4*)(&Ws[k * 132 + to * 8 + 4]);
        float wf[8] = {wa.x, wa.y, wa.z, wa.w, wb.x, wb.y, wb.z, wb.w};
#pragma unroll
        for (int oo = 0; oo < 8; oo++) {
            u64 w2 = bcast2(wf[oo]);
#pragma unroll
            for (int i = 0; i < 4; i++)
                fma2(acc2[oo][i], w2, px[i]);
        }
    }

    float acc[8][8];
#pragma unroll
    for (int oo = 0; oo < 8; oo++)
#pragma unroll
        for (int i = 0; i < 4; i++) {
            float2 f = unpk2(acc2[oo][i]);
            acc[oo][2*i] = f.x; acc[oo][2*i+1] = f.y;
        }

#pragma unroll
    for (int oo = 0; oo < 8; oo++) {
        int o = og * 128 + to * 8 + oo;
        float* dst;
        if (o < 192) {
            int g = o / 24, cc = o - g * 24;
            if (cc < 8) dst = &g_Kb[((g*8 + cc)      * H48 + h) * B2304];
            else        dst = &g_Vb[((g*16 + (cc-8)) * H48 + h) * B2304];
        } else {
            dst = &g_Q[((o - 192) * H48 + h) * B2304];
        }
        float4 v0 = make_float4(acc[oo][0], acc[oo][1], acc[oo][2], acc[oo][3]);
        float4 v1 = make_float4(acc[oo][4], acc[oo][5], acc[oo][6], acc[oo][7]);
        *(float4*)(dst + bb + ts * 8)     = v0;
        *(float4*)(dst + bb + ts * 8 + 4) = v1;

        float s1 = 0.f, s2 = 0.f;
#pragma unroll
        for (int i = 0; i < 8; i++) { s1 += acc[oo][i]; s2 = fmaf(acc[oo][i], acc[oo][i], s2); }
#pragma unroll
        for (int off = 1; off < 16; off <<= 1) {
            s1 += __shfl_xor_sync(0xffffffffu, s1, off);
            s2 += __shfl_xor_sync(0xffffffffu, s2, off);
        }
        if (ts == 0) {
            atomicAdd(&ss[(to * 8 + oo) * 2],     s1);
            atomicAdd(&ss[(to * 8 + oo) * 2 + 1], s2);
        }
    }
    __syncthreads();
    if (tid < 128) {
        int o = og * 128 + tid;
        atomicAdd(&g_projstats[2*o],   (double)ss[tid*2]);
        atomicAdd(&g_projstats[2*o+1], (double)ss[tid*2+1]);
    }
}

// ---------------- statsAB: merged per-position moments (A) + qk Grams (B) ----------------
__global__ __launch_bounds__(256)
void k_statsAB(const float* __restrict__ gkv, const float* __restrict__ bkv,
               const float* __restrict__ gq,  const float* __restrict__ bq) {
    __shared__ float red[8][88];
    __shared__ float tot[88];
    __shared__ float paq[8], pbq[8], pak[8], pbk[8];

    int tid = threadIdx.x;
    int g   = blockIdx.y;

    if (tid < 16) {
        int c = tid & 7;
        bool isq = tid < 8;
        int o = isq ? (192 + g*8 + c) : (g*24 + c);
        float gg = isq ? gq[g*8 + c] : gkv[o];
        float bb = isq ? bq[g*8 + c] : bkv[o];
        float a, sh; chan_affine(o, gg, bb, a, sh);
        if (isq) { paq[c] = a; pbq[c] = sh; }
        else     { pak[c] = a; pbk[c] = sh; }
    }
    __syncthreads();

    if (blockIdx.x < 48) {
        int i = blockIdx.x;
        const float* Qb = g_Q  + (g*384 + i) * B2304;
        const float* Kb = g_Kb + (g*384 + i) * B2304;

        float A[88];
#pragma unroll
        for (int t = 0; t < 88; t++) A[t] = 0.f;

#pragma unroll 3
        for (int ch = 0; ch < 9; ch++) {
            int b = tid + ch * 256;
            float qv[8], kv[8];
#pragma unroll
            for (int c = 0; c < 8; c++) qv[c] = Qb[c * (48*B2304) + b];
#pragma unroll
            for (int c = 0; c < 8; c++) kv[c] = Kb[c * (48*B2304) + b];
#pragma unroll
            for (int c = 0; c < 8; c++) { A[c] += qv[c]; A[44 + c] += kv[c]; }
            int p = 0;
#pragma unroll
            for (int c = 0; c < 8; c++)
#pragma unroll
                for (int c2 = c; c2 < 8; c2++) {
                    A[8 + p]  = fmaf(qv[c], qv[c2], A[8 + p]);
                    A[52 + p] = fmaf(kv[c], kv[c2], A[52 + p]);
                    p++;
                }
        }

        int lane = tid & 31, w = tid >> 5;
#pragma unroll
        for (int t = 0; t < 88; t++) {
            float v = A[t];
            v += __shfl_xor_sync(0xffffffffu, v, 16);
            v += __shfl_xor_sync(0xffffffffu, v, 8);
            v += __shfl_xor_sync(0xffffffffu, v, 4);
            v += __shfl_xor_sync(0xffffffffu, v, 2);
            v += __shfl_xor_sync(0xffffffffu, v, 1);
            if (lane == 0) red[w][t] = v;
        }
        __syncthreads();
        if (tid < 88) {
            float s = 0.f;
#pragma unroll
            for (int ww = 0; ww < 8; ww++) s += red[ww][tid];
            tot[tid] = s;
        }
        __syncthreads();
        if (tid < 88) {
            float s = tot[tid];
            const float N = (float)B2304;
            if (tid < 8) {
                int c = tid;
                g_SqTot[g][c][i] = paq[c] * s + N * pbq[c];
            } else if (tid < 44) {
                int p = tid - 8, c, c2; pair_cc(p, c, c2);
                float a1 = paq[c], b1 = pbq[c], a2 = paq[c2], b2 = pbq[c2];
                g_PqTot[g][p][i] = a1*a2*s + a1*b2*tot[c] + a2*b1*tot[c2] + N*b1*b2;
            } else if (tid < 52) {
                int c = tid - 44;
                g_SkTot[g][c][i] = pak[c] * s + N * pbk[c];
            } else {
                int p = tid - 52, c, c2; pair_cc(p, c, c2);
                float a1 = pak[c], b1 = pbk[c], a2 = pak[c2], b2 = pbk[c2];
                g_PkTot[g][p][i] = a1*a2*s + a1*b2*tot[44 + c] + a2*b1*tot[44 + c2] + N*b1*b2;
            }
        }
    } else {
        int b = (blockIdx.x - 48) * 256 + tid;
        const float* Qb = g_Q  + (g*384) * B2304 + b;
        const float* Kb = g_Kb + (g*384) * B2304 + b;

        float A[88];
#pragma unroll
        for (int t = 0; t < 88; t++) A[t] = 0.f;

#pragma unroll 2
        for (int i = 0; i < 48; i++) {
            float qv[8], kv[8];
#pragma unroll
            for (int c = 0; c < 8; c++) qv[c] = Qb[(c*48 + i) * B2304];
#pragma unroll
            for (int c = 0; c < 8; c++) kv[c] = Kb[(c*48 + i) * B2304];
#pragma unroll
            for (int c = 0; c < 8; c++) { A[c] += qv[c]; A[44 + c] += kv[c]; }
            int p = 0;
#pragma unroll
            for (int c = 0; c < 8; c++)
#pragma unroll
                for (int c2 = c; c2 < 8; c2++) {
                    A[8 + p]  = fmaf(qv[c], qv[c2], A[8 + p]);
                    A[52 + p] = fmaf(kv[c], kv[c2], A[52 + p]);
                    p++;
                }
        }

        float Rq[8], Rk[8];
#pragma unroll
        for (int c = 0; c < 8; c++) {
            Rq[c] = fmaf(paq[c], A[c],      48.f * pbq[c]);
            Rk[c] = fmaf(pak[c], A[44 + c], 48.f * pbk[c]);
        }
        float s1 = 0.f;
#pragma unroll
        for (int c = 0; c < 8; c++) s1 = fmaf(Rq[c], Rk[c], s1);

        float s2 = 0.f;
        {
            int p = 0;
#pragma unroll
            for (int c = 0; c < 8; c++)
#pragma unroll
                for (int c2 = c; c2 < 8; c2++) {
                    float Gq = paq[c]*paq[c2]*A[8 + p]  + paq[c]*pbq[c2]*A[c]
                             + paq[c2]*pbq[c]*A[c2]     + 48.f*pbq[c]*pbq[c2];
                    float Gk = pak[c]*pak[c2]*A[52 + p] + pak[c]*pbk[c2]*A[44 + c]
                             + pak[c2]*pbk[c]*A[44 + c2] + 48.f*pbk[c]*pbk[c2];
                    float w = (c == c2) ? 1.f : 2.f;
                    s2 = fmaf(w * Gq, Gk, s2);
                    p++;
                }
        }

        double d1 = (double)s1, d2 = (double)s2;
#pragma unroll
        for (int off = 16; off; off >>= 1) {
            d1 += __shfl_xor_sync(0xffffffffu, d1, off);
            d2 += __shfl_xor_sync(0xffffffffu, d2, off);
        }
        if ((tid & 31) == 0) {
            atomicAdd(&g_qkstat[g][0], d1);
            atomicAdd(&g_qkstat[g][1], d2);
        }
    }
}

// ---------------- finalize sim BN coefficients ----------------
__global__ __launch_bounds__(256)
void k_simfin(const float* __restrict__ rel,
              const float* __restrict__ gsim, const float* __restrict__ bsim,
              const float* __restrict__ fqr,  const float* __restrict__ fkr) {
    __shared__ float relq_s[8*RELW], relk_s[8*RELW];
    __shared__ float Rq[384], Rk[384];
    __shared__ float ERq[1728], ERk[1728];
    __shared__ double warp_out[8][4];

    int tid = threadIdx.x;
    for (int i = tid; i < 16*RELW; i += 256) {
        if (i < 8*RELW) relq_s[i] = rel[i];
        else            relk_s[i - 8*RELW] = rel[i];
    }
    __syncthreads();

    for (int it = tid; it < 384; it += 256) {
        int c = it / 48, i = it - (it/48)*48;
        float s = 0.f, sk = 0.f;
#pragma unroll 8
        for (int d = 0; d < 48; d++) {
            s  += relq_s[c*RELW + i + d];
            sk += relk_s[c*RELW + i + d];
        }
        Rq[it] = s; Rk[it] = sk;
    }
    for (int it = tid; it < 1728; it += 256) {
        int p = it / 48, i = it - (it/48)*48;
        int c, c2; pair_cc(p, c, c2);
        float s = 0.f, sk = 0.f;
#pragma unroll 8
        for (int d = 0; d < 48; d++) {
            s  = fmaf(relq_s[c*RELW + i + d], relq_s[c2*RELW + i + d], s);
            sk = fmaf(relk_s[c*RELW + i + d], relk_s[c2*RELW + i + d], sk);
        }
        ERq[it] = s; ERk[it] = sk;
    }
    __syncthreads();

    int w = tid >> 5, lane = tid & 31;
    int g = w;
    double qr_s = 0.0, qr_q = 0.0, kr_s = 0.0, kr_q = 0.0;
    for (int it = lane; it < 384; it += 32) {
        int c = it / 48, i = it - (it/48)*48;
        qr_s += (double)g_SqTot[g][c][i] * (double)Rq[it];
        kr_s += (double)g_SkTot[g][c][i] * (double)Rk[it];
    }
    for (int it = lane; it < 1728; it += 32) {
        int p = it / 48, i = it - (it/48)*48;
        int c, c2; pair_cc(p, c, c2);
        double ww = (c == c2) ? 1.0 : 2.0;
        qr_q += ww * (double)g_PqTot[g][p][i] * (double)ERq[it];
        kr_q += ww * (double)g_PkTot[g][p][i] * (double)ERk[it];
    }
#pragma unroll
    for (int off = 16; off; off >>= 1) {
        qr_s += __shfl_xor_sync(0xffffffffu, qr_s, off);
        qr_q += __shfl_xor_sync(0xffffffffu, qr_q, off);
        kr_s += __shfl_xor_sync(0xffffffffu, kr_s, off);
        kr_q += __shfl_xor_sync(0xffffffffu, kr_q, off);
    }
    if (lane == 0) {
        warp_out[w][0] = qr_s; warp_out[w][1] = qr_q;
        warp_out[w][2] = kr_s; warp_out[w][3] = kr_q;
    }
    __syncthreads();
    if (tid < 8) {
        int gg = tid;
        double N = (double)B2304 * 48.0 * 48.0;
        double fq = (double)(*fqr), fk = (double)(*fkr);

        double m0 = g_qkstat[gg][0] / N;
        double v0 = g_qkstat[gg][1] / N - m0 * m0;
        double m1 = fq * warp_out[gg][0] / N;
        double v1 = fq * fq * warp_out[gg][1] / N - m1 * m1;
        double m2 = fk * warp_out[gg][2] / N;
        double v2 = fk * fk * warp_out[gg][3] / N - m2 * m2;

        double i0 = 1.0 / sqrt(v0 + (double)EPS);
        double i1 = 1.0 / sqrt(v1 + (double)EPS);
        double i2 = 1.0 / sqrt(v2 + (double)EPS);

        double a0 = (double)gsim[0*G8 + gg] * i0;
        double a1 = (double)gsim[1*G8 + gg] * i1;
        double a2 = (double)gsim[2*G8 + gg] * i2;
        double shift = (double)bsim[0*G8+gg] - a0*m0
                     + (double)bsim[1*G8+gg] - a1*m1
                     + (double)bsim[2*G8+gg] - a2*m2;
        g_simco[gg*4+0] = (float)a0;
        g_simco[gg*4+1] = (float)(a1 * fq);
        g_simco[gg*4+2] = (float)(a2 * fk);
        g_simco[gg*4+3] = (float)shift;
    }
}

// ---------------- attention: R13 structure + paired-bl sv (rv amortized x2) ----------
#define BTL 8
// Qs 3072 + Ks 3072 + Vs 6144 + sim 2*2352 + rq 760 + rk 760 + rv 1520 = 20032 floats
#define AT_SMEM (20032 * 4)
__global__ __launch_bounds__(256, 2)
void k_attn(const float* __restrict__ rel,
            const float* __restrict__ fsv, const float* __restrict__ fsve,
            const float* __restrict__ gkv, const float* __restrict__ bkv,
            const float* __restrict__ gq,  const float* __restrict__ bq) {
    extern __shared__ float sm[];
    float* Qs   = sm;                    // [bl][i][8]  (pre-scaled by A0)
    float* Ks   = Qs + BTL*48*8;         // [bl][j][8]
    float* Vs   = Ks + BTL*48*8;         // [bl][j][16] (f_sv folded)
    float* simA = Vs + BTL*48*16;        // 2 x [48][49]
    float* rq_t = simA + 2*48*49;        // [d][8]   (pre-scaled by A1/A0)
    float* rk_t = rq_t + RELW*8;         // [d][8]   (pre-scaled by A2)
    float* rv_t = rk_t + RELW*8;         // [d][16]  (pre-scaled by f_sve)
    __shared__ double red[64];
    __shared__ float pa_s[32], pb_s[32]; // 0-7 q, 8-15 k, 16-31 v

    int tid = threadIdx.x;
    int g   = blockIdx.y;
    int b0  = blockIdx.x * BTL;

    float A0 = g_simco[g*4+0], A1 = g_simco[g*4+1];
    float A2 = g_simco[g*4+2], SH = g_simco[g*4+3];
    float A1oA0 = A1 / A0;
    float vsv = *fsv, vsve = *fsve;

    if (tid < 32) {
        int o; float gg, bb;
        if (tid < 8)       { o = 192 + g*8 + tid;   gg = gq[g*8 + tid];  bb = bq[g*8 + tid]; }
        else if (tid < 16) { o = g*24 + (tid - 8);  gg = gkv[o];         bb = bkv[o]; }
        else               { o = g*24 + 8 + (tid - 16); gg = gkv[o];     bb = bkv[o]; }
        float a, sh; chan_affine(o, gg, bb, a, sh);
        pa_s[tid] = a; pb_s[tid] = sh;
    }
    __syncthreads();

    for (int i = tid; i < RELW*8; i += 256) {
        int d = i >> 3, c = i & 7;
        rq_t[i] = rel[c*RELW + d] * A1oA0;
        rk_t[i] = rel[(8 + c)*RELW + d] * A2;
    }
    for (int i = tid; i < RELW*16; i += 256) {
        int d = i >> 4, c = i & 15;
        rv_t[i] = rel[(16 + c)*RELW + d] * vsve;
    }
#pragma unroll
    for (int it = 0; it < 3; it++) {
        int idx = tid + it * 256;
        int row = idx >> 1, q = idx & 1;
        int c = row / 48, i = row % 48;
        float4 vq = *(const float4*)(&g_Q [(g*384 + row) * B2304 + b0 + q*4]);
        float4 vk = *(const float4*)(&g_Kb[(g*384 + row) * B2304 + b0 + q*4]);
        float aq = pa_s[c] * A0, bqv = pb_s[c] * A0;   // fold A0 into Q
        float ak = pa_s[8 + c], bkv2 = pb_s[8 + c];
        float qv[4] = {vq.x, vq.y, vq.z, vq.w};
        float kv[4] = {vk.x, vk.y, vk.z, vk.w};
#pragma unroll
        for (int e = 0; e < 4; e++) {
            Qs[(q*4 + e)*384 + i*8 + c] = fmaf(aq, qv[e], bqv);
            Ks[(q*4 + e)*384 + i*8 + c] = fmaf(ak, kv[e], bkv2);
        }
    }
#pragma unroll
    for (int it = 0; it < 6; it++) {
        int idx = tid + it * 256;
        int row = idx >> 1, q = idx & 1;
        int c = row / 48, j = row % 48;
        float4 vv = *(const float4*)(&g_Vb[(g*768 + row) * B2304 + b0 + q*4]);
        float av = pa_s[16 + c] * vsv, bv = pb_s[16 + c] * vsv;
        float vf[4] = {vv.x, vv.y, vv.z, vv.w};
#pragma unroll
        for (int e = 0; e < 4; e++)
            Vs[(q*4 + e)*768 + j*16 + c] = fmaf(av, vf[e], bv);
    }
    for (int i = tid; i < 64; i += 256) red[i] = 0.0;
    __syncthreads();

    int ti = tid >> 4, tj = tid & 15;
    int i0 = ti * 3, j0 = tj * 3;
    int Dq = i0 - j0 + 47;     // rq row for (r,s): Dq + r - s
    int Dk = j0 - i0 + 47;     // rk row for (r,s): Dk + s - r

    int sv_i  = tid >> 2;
    int sv_c0 = (tid & 3) * 4;

    float lsv_s[4]  = {0,0,0,0}, lsv_q[4]  = {0,0,0,0};
    float lsve_s[4] = {0,0,0,0}, lsve_q[4] = {0,0,0,0};

    for (int bl0 = 0; bl0 < BTL; bl0 += 2) {
        // ---- logits + softmax for the pair (bl0, bl0+1) ----
#pragma unroll
        for (int h = 0; h < 2; h++) {
            int bl = bl0 + h;
            const float* Q = Qs + bl*384;
            const float* K = Ks + bl*384;
            float* sim = simA + h*2352;

            u64 k2[3][4];
#pragma unroll
            for (int s = 0; s < 3; s++) {
                ulonglong2 a = *(const ulonglong2*)(&K[(j0 + s)*8]);
                ulonglong2 b = *(const ulonglong2*)(&K[(j0 + s)*8 + 4]);
                k2[s][0] = a.x; k2[s][1] = a.y; k2[s][2] = b.x; k2[s][3] = b.y;
            }
            u64 acc[3][3];
#pragma unroll
            for (int r = 0; r < 3; r++)
#pragma unroll
                for (int s = 0; s < 3; s++) acc[r][s] = 0ull;

#pragma unroll
            for (int r = 0; r < 3; r++) {
                u64 q2[4];
                {
                    ulonglong2 a = *(const ulonglong2*)(&Q[(i0 + r)*8]);
                    ulonglong2 b = *(const ulonglong2*)(&Q[(i0 + r)*8 + 4]);
                    q2[0] = a.x; q2[1] = a.y; q2[2] = b.x; q2[3] = b.y;
                }
#pragma unroll
                for (int cp = 0; cp < 4; cp++)
#pragma unroll
                    for (int s = 0; s < 3; s++)
                        fma2(acc[r][s], q2[cp], k2[s][cp]);
#pragma unroll
                for (int s = 0; s < 3; s++) {
                    const float* rr = &rq_t[(Dq + r - s)*8];
                    ulonglong2 a = *(const ulonglong2*)(rr);
                    ulonglong2 b = *(const ulonglong2*)(rr + 4);
                    fma2(acc[r][s], q2[0], a.x); fma2(acc[r][s], q2[1], a.y);
                    fma2(acc[r][s], q2[2], b.x); fma2(acc[r][s], q2[3], b.y);
                }
            }
#pragma unroll
            for (int s = 0; s < 3; s++)
#pragma unroll
                for (int r = 0; r < 3; r++) {
                    const float* rr = &rk_t[(Dk + s - r)*8];
                    ulonglong2 a = *(const ulonglong2*)(rr);
                    ulonglong2 b = *(const ulonglong2*)(rr + 4);
                    fma2(acc[r][s], k2[s][0], a.x); fma2(acc[r][s], k2[s][1], a.y);
                    fma2(acc[r][s], k2[s][2], b.x); fma2(acc[r][s], k2[s][3], b.y);
                }

            float e[3][3], rs[3];
#pragma unroll
            for (int r = 0; r < 3; r++) {
                rs[r] = 0.f;
#pragma unroll
                for (int s = 0; s < 3; s++) {
                    float2 aa = unpk2(acc[r][s]);
                    e[r][s] = __expf(aa.x + aa.y + SH);
                    rs[r] += e[r][s];
                }
            }
#pragma unroll
            for (int off = 1; off < 16; off <<= 1) {
#pragma unroll
                for (int r = 0; r < 3; r++)
                    rs[r] += __shfl_xor_sync(0xffffffffu, rs[r], off);
            }
#pragma unroll
            for (int r = 0; r < 3; r++) {
                float rinv = 1.f / rs[r];
#pragma unroll
                for (int s = 0; s < 3; s++)
                    sim[(i0 + r)*49 + j0 + s] = e[r][s] * rinv;
            }
        }
        __syncthreads();

        // ---- sv / sve for the pair: one rv load serves both bl ----
        if (tid < 192) {
            u64 sv2[2][2] = {{0ull,0ull},{0ull,0ull}};
            u64 se2[2][2] = {{0ull,0ull},{0ull,0ull}};
            const float* simr0 = &simA[sv_i*49];
            const float* simr1 = &simA[2352 + sv_i*49];
            const float* V0 = Vs + bl0*768;
            const float* V1 = V0 + 768;
#pragma unroll 4
            for (int j = 0; j < 48; j++) {
                ulonglong2 rv = *(const ulonglong2*)(&rv_t[(sv_i - j + 47)*16 + sv_c0]);
                {
                    u64 s2 = bcast2(simr0[j]);
                    ulonglong2 v = *(const ulonglong2*)(&V0[j*16 + sv_c0]);
                    fma2(sv2[0][0], s2, v.x);  fma2(sv2[0][1], s2, v.y);
                    fma2(se2[0][0], s2, rv.x); fma2(se2[0][1], s2, rv.y);
                }
                {
                    u64 s2 = bcast2(simr1[j]);
                    ulonglong2 v = *(const ulonglong2*)(&V1[j*16 + sv_c0]);
                    fma2(sv2[1][0], s2, v.x);  fma2(sv2[1][1], s2, v.y);
                    fma2(se2[1][0], s2, rv.x); fma2(se2[1][1], s2, rv.y);
                }
            }
#pragma unroll
            for (int h = 0; h < 2; h++) {
                int b = b0 + bl0 + h;
                float* outv = &g_SV [b*6144 + g*768 + sv_c0*48 + sv_i];
                float* oute = &g_SVE[b*6144 + g*768 + sv_c0*48 + sv_i];
                float2 f0 = unpk2(sv2[h][0]), f1 = unpk2(sv2[h][1]);
                float2 g0 = unpk2(se2[h][0]), g1 = unpk2(se2[h][1]);
                float svv[4] = {f0.x, f0.y, f1.x, f1.y};
                float sev[4] = {g0.x, g0.y, g1.x, g1.y};
#pragma unroll
                for (int cc = 0; cc < 4; cc++) {
                    outv[cc*48] = svv[cc];
                    oute[cc*48] = sev[cc];
                    lsv_s[cc]  += svv[cc]; lsv_q[cc]  += svv[cc]*svv[cc];
                    lsve_s[cc] += sev[cc]; lsve_q[cc] += sev[cc]*sev[cc];
                }
            }
        }
        __syncthreads();
    }

    if (tid < 192) {
#pragma unroll
        for (int cc = 0; cc < 4; cc++) {
            int c = sv_c0 + cc;
            atomicAdd(&red[c*4+0], (double)lsv_s[cc]);
            atomicAdd(&red[c*4+1], (double)lsv_q[cc]);
            atomicAdd(&red[c*4+2], (double)lsve_s[cc]);
            atomicAdd(&red[c*4+3], (double)lsve_q[cc]);
        }
    }
    __syncthreads();
    if (tid < 16) {
        int o_sv  = (g*16 + tid)*2;
        int o_sve = o_sv + 1;
        atomicAdd(&g_outstats[o_sv*2+0],  red[tid*4+0]);
        atomicAdd(&g_outstats[o_sv*2+1],  red[tid*4+1]);
        atomicAdd(&g_outstats[o_sve*2+0], red[tid*4+2]);
        atomicAdd(&g_outstats[o_sve*2+1], red[tid*4+3]);
    }
}

// ---------------- out BN coefficients + restore accumulators to zero ----------------
__global__ void k_outco(const float* __restrict__ gout, const float* __restrict__ bout) {
    int o = threadIdx.x;
    double N = (double)P110592;
    double s1 = g_outstats[2*o], s2 = g_outstats[2*o+1];
    double mean = s1 / N, var = s2 / N - mean * mean;
    float inv = rsqrtf((float)var + EPS);
    float A = gout[o] * inv;
    g_oA[o] = A;
    g_oC[o] = bout[o] - A * (float)mean;
    g_outstats[2*o] = 0.0;  g_outstats[2*o+1] = 0.0;
    g_projstats[2*o] = 0.0; g_projstats[2*o+1] = 0.0;
    if (o < G8*2) ((double*)g_qkstat)[o] = 0.0;
}

// ---------------- final: affine-combine + transpose [b][r] -> [r][b] ----------------
__global__ __launch_bounds__(256)
void k_final(float* __restrict__ out) {
    __shared__ float tile[32][33];
    int r0 = blockIdx.x * 32;
    int b0 = blockIdx.y * 32;
    int tx = threadIdx.x, ty = threadIdx.y;

    int r = r0 + tx;
    int gc = r / 48;
    float Asv  = g_oA[gc*2],   Csv  = g_oC[gc*2];
    float Asve = g_oA[gc*2+1], Csve = g_oC[gc*2+1];
#pragma unroll
    for (int k = 0; k < 4; k++) {
        int b = b0 + ty + k*8;
        float v = Asv * g_SV[b*6144 + r] + Csv
                + Asve * g_SVE[b*6144 + r] + Csve;
        tile[ty + k*8][tx] = v;
    }
    __syncthreads();
#pragma unroll
    for (int k = 0; k < 4; k++) {
        int rr = r0 + ty + k*8;
        out[rr * B2304 + b0 + tx] = tile[tx][ty + k*8];
    }
}

// ---------------- launch ----------------
extern "C" void kernel_launch(void* const* d_in, const int* in_sizes, int n_in,
                              void* d_out, int out_size) {
    const float* x    = (const float*)d_in[0];
    const float* Wkv  = (const float*)d_in[1];
    const float* Wq   = (const float*)d_in[2];
    const float* gkv  = (const float*)d_in[3];
    const float* bkv  = (const float*)d_in[4];
    const float* gq   = (const float*)d_in[5];
    const float* bq   = (const float*)d_in[6];
    const float* gsim = (const float*)d_in[7];
    const float* bsim = (const float*)d_in[8];
    const float* gout = (const float*)d_in[9];
    const float* bout = (const float*)d_in[10];
    const float* rel  = (const float*)d_in[11];
    const float* fqr  = (const float*)d_in[12];
    const float* fkr  = (const float*)d_in[13];
    const float* fsv  = (const float*)d_in[14];
    const float* fsve = (const float*)d_in[15];
    float* out = (float*)d_out;

    cudaFuncSetAttribute(k_proj, cudaFuncAttributeMaxDynamicSharedMemorySize, PJ_SMEM);
    cudaFuncSetAttribute(k_attn, cudaFuncAttributeMaxDynamicSharedMemorySize, AT_SMEM);

    k_proj<<<dim3(P110592/128, 2), 256, PJ_SMEM>>>(x, Wkv, Wq);
    k_statsAB<<<dim3(48 + B2304/256, G8), 256>>>(gkv, bkv, gq, bq);
    k_simfin<<<1, 256>>>(rel, gsim, bsim, fqr, fkr);
    k_attn<<<dim3(B2304/BTL, G8), 256, AT_SMEM>>>(rel, fsv, fsve, gkv, bkv, gq, bq);
    k_outco<<<1, 256>>>(gout, bout);
    k_final<<<dim3(6144/32, B2304/32), dim3(32, 8)>>>(out);
}

// round 16
// speedup vs baseline: 1.3060x; 1.0140x over previous
#include <cuda_runtime.h>

// ---------------- problem constants ----------------
#define G8      8
#define DK8     8
#define DV16    16
#define CIN64   64
#define H48     48
#define B2304   2304
#define P110592 110592      // B * H
#define NOUT    256         // 192 kv rows + 64 q rows
#define RELW    95          // 2K-1
#define EPS     1e-5f

typedef unsigned long long u64;

// ---- packed f32x2 helpers ----
__device__ __forceinline__ void fma2(u64& d, u64 a, u64 b) {
    asm("fma.rn.f32x2 %0, %1, %2, %0;" : "+l"(d) : "l"(a), "l"(b));
}
__device__ __forceinline__ u64 bcast2(float v) {
    u64 r; asm("mov.b64 %0, {%1, %1};" : "=l"(r) : "f"(v)); return r;
}
__device__ __forceinline__ float2 unpk2(u64 v) {
    float2 f; asm("mov.b64 {%0, %1}, %2;" : "=f"(f.x), "=f"(f.y) : "l"(v)); return f;
}

// ---------------- scratch (device globals; zero-initialized at load,
//                  re-zeroed by k_outco each call -> replay-invariant) ----
__device__ float  g_Q  [G8*DK8*H48*B2304];   // [(g*8+c)*48+h][b]  raw projection
__device__ float  g_Kb [G8*DK8*H48*B2304];
__device__ float  g_Vb [G8*DV16*H48*B2304];
__device__ float  g_SV [B2304*G8*DV16*H48];  // [b][(g*16+c)*48+i]
__device__ float  g_SVE[B2304*G8*DV16*H48];
__device__ double g_projstats[NOUT*2];
__device__ float  g_simco[G8*4];
__device__ double g_outstats[NOUT*2];
__device__ float  g_oA[NOUT], g_oC[NOUT];

__device__ float  g_SqTot[G8][8][48];
__device__ float  g_SkTot[G8][8][48];
__device__ float  g_PqTot[G8][36][48];
__device__ float  g_PkTot[G8][36][48];
__device__ double g_qkstat[G8][2];

__device__ __forceinline__ void pair_cc(int p, int& c, int& c2) {
    int base = 0, cc = 0;
#pragma unroll
    for (int r = 0; r < 8; r++) {
        int cnt = 8 - r;
        if (p < base + cnt) { cc = r; break; }
        base += cnt;
    }
    c = cc; c2 = cc + (p - base);
}

__device__ __forceinline__ void chan_affine(int o, float gg, float bb,
                                            float& a, float& sh) {
    double s1 = g_projstats[2*o], s2 = g_projstats[2*o+1];
    double mean = s1 / (double)P110592;
    double var  = s2 / (double)P110592 - mean * mean;
    float inv = rsqrtf((float)var + EPS);
    a  = gg * inv;
    sh = bb - a * (float)mean;
}

// ---------------- projection GEMM: packed-f32x2 mainloop ----------------
#define PJ_SMEM ((64*128 + 64*132 + 256) * 4)
__global__ __launch_bounds__(256, 2)
void k_proj(const float* __restrict__ x,
            const float* __restrict__ Wkv,
            const float* __restrict__ Wq) {
    extern __shared__ float sm[];
    float* Xs = sm;                // [64][128]
    float* Ws = Xs + 64*128;       // [64][132]
    float* ss = Ws + 64*132;       // [128][2] block stats

    int tid = threadIdx.x;
    int ts = tid & 15, to = tid >> 4;
    int og = blockIdx.y;
    int s0 = blockIdx.x * 128;
    int h  = s0 / B2304;
    int bb = s0 - h * B2304;

    if (tid < 256) ss[tid] = 0.f;

#pragma unroll
    for (int it = 0; it < 8; it++) {
        int i = tid + it * 256;
        int c = i >> 5, q = i & 31;
        float4 v = *(const float4*)(x + c * P110592 + s0 + q * 4);
        *(float4*)(&Xs[c * 128 + q * 4]) = v;
    }
#pragma unroll
    for (int it = 0; it < 8; it++) {
        int i = tid + it * 256;
        int o_l = i >> 4, q = i & 15;
        int o = og * 128 + o_l;
        float4 w = (o < 192) ? *(const float4*)(Wkv + o * 64 + q * 4)
                             : *(const float4*)(Wq + (o - 192) * 64 + q * 4);
        int k0 = q * 4;
        Ws[(k0 + 0) * 132 + o_l] = w.x;
        Ws[(k0 + 1) * 132 + o_l] = w.y;
        Ws[(k0 + 2) * 132 + o_l] = w.z;
        Ws[(k0 + 3) * 132 + o_l] = w.w;
    }
    __syncthreads();

    u64 acc2[8][4];
#pragma unroll
    for (int a = 0; a < 8; a++)
#pragma unroll
        for (int b = 0; b < 4; b++) acc2[a][b] = 0ull;

#pragma unroll 4
    for (int k = 0; k < 64; k++) {
        ulonglong2 xa = *(ulonglong2*)(&Xs[k * 128 + ts * 8]);
        ulonglong2 xb = *(ulonglong2*)(&Xs[k * 128 + ts * 8 + 4]);
        u64 px[4] = {xa.x, xa.y, xb.x, xb.y};
        float4 wa = *(float4*)(&Ws[k * 132 + to * 8]);
        float4 wb = *(float4*)(&Ws[k * 132 + to * 8 + 4]);
        float wf[8] = {wa.x, wa.y, wa.z, wa.w, wb.x, wb.y, wb.z, wb.w};
#pragma unroll
        for (int oo = 0; oo < 8; oo++) {
            u64 w2 = bcast2(wf[oo]);
#pragma unroll
            for (int i = 0; i < 4; i++)
                fma2(acc2[oo][i], w2, px[i]);
        }
    }

    float acc[8][8];
#pragma unroll
    for (int oo = 0; oo < 8; oo++)
#pragma unroll
        for (int i = 0; i < 4; i++) {
            float2 f = unpk2(acc2[oo][i]);
            acc[oo][2*i] = f.x; acc[oo][2*i+1] = f.y;
        }

#pragma unroll
    for (int oo = 0; oo < 8; oo++) {
        int o = og * 128 + to * 8 + oo;
        float* dst;
        if (o < 192) {
            int g = o / 24, cc = o - g * 24;
            if (cc < 8) dst = &g_Kb[((g*8 + cc)      * H48 + h) * B2304];
            else        dst = &g_Vb[((g*16 + (cc-8)) * H48 + h) * B2304];
        } else {
            dst = &g_Q[((o - 192) * H48 + h) * B2304];
        }
        float4 v0 = make_float4(acc[oo][0], acc[oo][1], acc[oo][2], acc[oo][3]);
        float4 v1 = make_float4(acc[oo][4], acc[oo][5], acc[oo][6], acc[oo][7]);
        *(float4*)(dst + bb + ts * 8)     = v0;
        *(float4*)(dst + bb + ts * 8 + 4) = v1;

        float s1 = 0.f, s2 = 0.f;
#pragma unroll
        for (int i = 0; i < 8; i++) { s1 += acc[oo][i]; s2 = fmaf(acc[oo][i], acc[oo][i], s2); }
#pragma unroll
        for (int off = 1; off < 16; off <<= 1) {
            s1 += __shfl_xor_sync(0xffffffffu, s1, off);
            s2 += __shfl_xor_sync(0xffffffffu, s2, off);
        }
        if (ts == 0) {
            atomicAdd(&ss[(to * 8 + oo) * 2],     s1);
            atomicAdd(&ss[(to * 8 + oo) * 2 + 1], s2);
        }
    }
    __syncthreads();
    if (tid < 128) {
        int o = og * 128 + tid;
        atomicAdd(&g_projstats[2*o],   (double)ss[tid*2]);
        atomicAdd(&g_projstats[2*o+1], (double)ss[tid*2+1]);
    }
}

// ---------------- statsAB: merged per-position moments (A) + qk Grams (B) ----------------
__global__ __launch_bounds__(256)
void k_statsAB(const float* __restrict__ gkv, const float* __restrict__ bkv,
               const float* __restrict__ gq,  const float* __restrict__ bq) {
    __shared__ float red[8][88];
    __shared__ float tot[88];
    __shared__ float paq[8], pbq[8], pak[8], pbk[8];

    int tid = threadIdx.x;
    int g   = blockIdx.y;

    if (tid < 16) {
        int c = tid & 7;
        bool isq = tid < 8;
        int o = isq ? (192 + g*8 + c) : (g*24 + c);
        float gg = isq ? gq[g*8 + c] : gkv[o];
        float bb = isq ? bq[g*8 + c] : bkv[o];
        float a, sh; chan_affine(o, gg, bb, a, sh);
        if (isq) { paq[c] = a; pbq[c] = sh; }
        else     { pak[c] = a; pbk[c] = sh; }
    }
    __syncthreads();

    if (blockIdx.x < 48) {
        int i = blockIdx.x;
        const float* Qb = g_Q  + (g*384 + i) * B2304;
        const float* Kb = g_Kb + (g*384 + i) * B2304;

        float A[88];
#pragma unroll
        for (int t = 0; t < 88; t++) A[t] = 0.f;

#pragma unroll 3
        for (int ch = 0; ch < 9; ch++) {
            int b = tid + ch * 256;
            float qv[8], kv[8];
#pragma unroll
            for (int c = 0; c < 8; c++) qv[c] = Qb[c * (48*B2304) + b];
#pragma unroll
            for (int c = 0; c < 8; c++) kv[c] = Kb[c * (48*B2304) + b];
#pragma unroll
            for (int c = 0; c < 8; c++) { A[c] += qv[c]; A[44 + c] += kv[c]; }
            int p = 0;
#pragma unroll
            for (int c = 0; c < 8; c++)
#pragma unroll
                for (int c2 = c; c2 < 8; c2++) {
                    A[8 + p]  = fmaf(qv[c], qv[c2], A[8 + p]);
                    A[52 + p] = fmaf(kv[c], kv[c2], A[52 + p]);
                    p++;
                }
        }

        int lane = tid & 31, w = tid >> 5;
#pragma unroll
        for (int t = 0; t < 88; t++) {
            float v = A[t];
            v += __shfl_xor_sync(0xffffffffu, v, 16);
            v += __shfl_xor_sync(0xffffffffu, v, 8);
            v += __shfl_xor_sync(0xffffffffu, v, 4);
            v += __shfl_xor_sync(0xffffffffu, v, 2);
            v += __shfl_xor_sync(0xffffffffu, v, 1);
            if (lane == 0) red[w][t] = v;
        }
        __syncthreads();
        if (tid < 88) {
            float s = 0.f;
#pragma unroll
            for (int ww = 0; ww < 8; ww++) s += red[ww][tid];
            tot[tid] = s;
        }
        __syncthreads();
        if (tid < 88) {
            float s = tot[tid];
            const float N = (float)B2304;
            if (tid < 8) {
                int c = tid;
                g_SqTot[g][c][i] = paq[c] * s + N * pbq[c];
            } else if (tid < 44) {
                int p = tid - 8, c, c2; pair_cc(p, c, c2);
                float a1 = paq[c], b1 = pbq[c], a2 = paq[c2], b2 = pbq[c2];
                g_PqTot[g][p][i] = a1*a2*s + a1*b2*tot[c] + a2*b1*tot[c2] + N*b1*b2;
            } else if (tid < 52) {
                int c = tid - 44;
                g_SkTot[g][c][i] = pak[c] * s + N * pbk[c];
            } else {
                int p = tid - 52, c, c2; pair_cc(p, c, c2);
                float a1 = pak[c], b1 = pbk[c], a2 = pak[c2], b2 = pbk[c2];
                g_PkTot[g][p][i] = a1*a2*s + a1*b2*tot[44 + c] + a2*b1*tot[44 + c2] + N*b1*b2;
            }
        }
    } else {
        int b = (blockIdx.x - 48) * 256 + tid;
        const float* Qb = g_Q  + (g*384) * B2304 + b;
        const float* Kb = g_Kb + (g*384) * B2304 + b;

        float A[88];
#pragma unroll
        for (int t = 0; t < 88; t++) A[t] = 0.f;

#pragma unroll 2
        for (int i = 0; i < 48; i++) {
            float qv[8], kv[8];
#pragma unroll
            for (int c = 0; c < 8; c++) qv[c] = Qb[(c*48 + i) * B2304];
#pragma unroll
            for (int c = 0; c < 8; c++) kv[c] = Kb[(c*48 + i) * B2304];
#pragma unroll
            for (int c = 0; c < 8; c++) { A[c] += qv[c]; A[44 + c] += kv[c]; }
            int p = 0;
#pragma unroll
            for (int c = 0; c < 8; c++)
#pragma unroll
                for (int c2 = c; c2 < 8; c2++) {
                    A[8 + p]  = fmaf(qv[c], qv[c2], A[8 + p]);
                    A[52 + p] = fmaf(kv[c], kv[c2], A[52 + p]);
                    p++;
                }
        }

        float Rq[8], Rk[8];
#pragma unroll
        for (int c = 0; c < 8; c++) {
            Rq[c] = fmaf(paq[c], A[c],      48.f * pbq[c]);
            Rk[c] = fmaf(pak[c], A[44 + c], 48.f * pbk[c]);
        }
        float s1 = 0.f;
#pragma unroll
        for (int c = 0; c < 8; c++) s1 = fmaf(Rq[c], Rk[c], s1);

        float s2 = 0.f;
        {
            int p = 0;
#pragma unroll
            for (int c = 0; c < 8; c++)
#pragma unroll
                for (int c2 = c; c2 < 8; c2++) {
                    float Gq = paq[c]*paq[c2]*A[8 + p]  + paq[c]*pbq[c2]*A[c]
                             + paq[c2]*pbq[c]*A[c2]     + 48.f*pbq[c]*pbq[c2];
                    float Gk = pak[c]*pak[c2]*A[52 + p] + pak[c]*pbk[c2]*A[44 + c]
                             + pak[c2]*pbk[c]*A[44 + c2] + 48.f*pbk[c]*pbk[c2];
                    float w = (c == c2) ? 1.f : 2.f;
                    s2 = fmaf(w * Gq, Gk, s2);
                    p++;
                }
        }

        double d1 = (double)s1, d2 = (double)s2;
#pragma unroll
        for (int off = 16; off; off >>= 1) {
            d1 += __shfl_xor_sync(0xffffffffu, d1, off);
            d2 += __shfl_xor_sync(0xffffffffu, d2, off);
        }
        if ((tid & 31) == 0) {
            atomicAdd(&g_qkstat[g][0], d1);
            atomicAdd(&g_qkstat[g][1], d2);
        }
    }
}

// ---------------- finalize sim BN coefficients ----------------
__global__ __launch_bounds__(256)
void k_simfin(const float* __restrict__ rel,
              const float* __restrict__ gsim, const float* __restrict__ bsim,
              const float* __restrict__ fqr,  const float* __restrict__ fkr) {
    __shared__ float relq_s[8*RELW], relk_s[8*RELW];
    __shared__ float Rq[384], Rk[384];
    __shared__ float ERq[1728], ERk[1728];
    __shared__ double warp_out[8][4];

    int tid = threadIdx.x;
    for (int i = tid; i < 16*RELW; i += 256) {
        if (i < 8*RELW) relq_s[i] = rel[i];
        else            relk_s[i - 8*RELW] = rel[i];
    }
    __syncthreads();

    for (int it = tid; it < 384; it += 256) {
        int c = it / 48, i = it - (it/48)*48;
        float s = 0.f, sk = 0.f;
#pragma unroll 8
        for (int d = 0; d < 48; d++) {
            s  += relq_s[c*RELW + i + d];
            sk += relk_s[c*RELW + i + d];
        }
        Rq[it] = s; Rk[it] = sk;
    }
    for (int it = tid; it < 1728; it += 256) {
        int p = it / 48, i = it - (it/48)*48;
        int c, c2; pair_cc(p, c, c2);
        float s = 0.f, sk = 0.f;
#pragma unroll 8
        for (int d = 0; d < 48; d++) {
            s  = fmaf(relq_s[c*RELW + i + d], relq_s[c2*RELW + i + d], s);
            sk = fmaf(relk_s[c*RELW + i + d], relk_s[c2*RELW + i + d], sk);
        }
        ERq[it] = s; ERk[it] = sk;
    }
    __syncthreads();

    int w = tid >> 5, lane = tid & 31;
    int g = w;
    double qr_s = 0.0, qr_q = 0.0, kr_s = 0.0, kr_q = 0.0;
    for (int it = lane; it < 384; it += 32) {
        int c = it / 48, i = it - (it/48)*48;
        qr_s += (double)g_SqTot[g][c][i] * (double)Rq[it];
        kr_s += (double)g_SkTot[g][c][i] * (double)Rk[it];
    }
    for (int it = lane; it < 1728; it += 32) {
        int p = it / 48, i = it - (it/48)*48;
        int c, c2; pair_cc(p, c, c2);
        double ww = (c == c2) ? 1.0 : 2.0;
        qr_q += ww * (double)g_PqTot[g][p][i] * (double)ERq[it];
        kr_q += ww * (double)g_PkTot[g][p][i] * (double)ERk[it];
    }
#pragma unroll
    for (int off = 16; off; off >>= 1) {
        qr_s += __shfl_xor_sync(0xffffffffu, qr_s, off);
        qr_q += __shfl_xor_sync(0xffffffffu, qr_q, off);
        kr_s += __shfl_xor_sync(0xffffffffu, kr_s, off);
        kr_q += __shfl_xor_sync(0xffffffffu, kr_q, off);
    }
    if (lane == 0) {
        warp_out[w][0] = qr_s; warp_out[w][1] = qr_q;
        warp_out[w][2] = kr_s; warp_out[w][3] = kr_q;
    }
    __syncthreads();
    if (tid < 8) {
        int gg = tid;
        double N = (double)B2304 * 48.0 * 48.0;
        double fq = (double)(*fqr), fk = (double)(*fkr);

        double m0 = g_qkstat[gg][0] / N;
        double v0 = g_qkstat[gg][1] / N - m0 * m0;
        double m1 = fq * warp_out[gg][0] / N;
        double v1 = fq * fq * warp_out[gg][1] / N - m1 * m1;
        double m2 = fk * warp_out[gg][2] / N;
        double v2 = fk * fk * warp_out[gg][3] / N - m2 * m2;

        double i0 = 1.0 / sqrt(v0 + (double)EPS);
        double i1 = 1.0 / sqrt(v1 + (double)EPS);
        double i2 = 1.0 / sqrt(v2 + (double)EPS);

        double a0 = (double)gsim[0*G8 + gg] * i0;
        double a1 = (double)gsim[1*G8 + gg] * i1;
        double a2 = (double)gsim[2*G8 + gg] * i2;
        double shift = (double)bsim[0*G8+gg] - a0*m0
                     + (double)bsim[1*G8+gg] - a1*m1
                     + (double)bsim[2*G8+gg] - a2*m2;
        g_simco[gg*4+0] = (float)a0;
        g_simco[gg*4+1] = (float)(a1 * fq);
        g_simco[gg*4+2] = (float)(a2 * fk);
        g_simco[gg*4+3] = (float)shift;
    }
}

// ---------------- attention: 4-bl sv groups + float4 sim reads ----------
#define BTL 8
#define SIMP 52   // sim row pitch (16B-aligned rows: 52*4=208=13*16)
// Qs 3072 + Ks 3072 + Vs 6144 + sim 4*48*52=9984 + rq 760 + rk 760 + rv 1520 = 25312 floats
#define AT_SMEM (25312 * 4)
__global__ __launch_bounds__(256, 2)
void k_attn(const float* __restrict__ rel,
            const float* __restrict__ fsv, const float* __restrict__ fsve,
            const float* __restrict__ gkv, const float* __restrict__ bkv,
            const float* __restrict__ gq,  const float* __restrict__ bq) {
    extern __shared__ float sm[];
    float* Qs   = sm;                    // [bl][i][8]  (pre-scaled by A0)
    float* Ks   = Qs + BTL*48*8;         // [bl][j][8]
    float* Vs   = Ks + BTL*48*8;         // [bl][j][16] (f_sv folded)
    float* simA = Vs + BTL*48*16;        // 4 x [48][SIMP]
    float* rq_t = simA + 4*48*SIMP;      // [d][8]   (pre-scaled by A1/A0)
    float* rk_t = rq_t + RELW*8;         // [d][8]   (pre-scaled by A2)
    float* rv_t = rk_t + RELW*8;         // [d][16]  (pre-scaled by f_sve)
    __shared__ double red[64];
    __shared__ float pa_s[32], pb_s[32]; // 0-7 q, 8-15 k, 16-31 v

    int tid = threadIdx.x;
    int g   = blockIdx.y;
    int b0  = blockIdx.x * BTL;

    float A0 = g_simco[g*4+0], A1 = g_simco[g*4+1];
    float A2 = g_simco[g*4+2], SH = g_simco[g*4+3];
    float A1oA0 = A1 / A0;
    float vsv = *fsv, vsve = *fsve;

    if (tid < 32) {
        int o; float gg, bb;
        if (tid < 8)       { o = 192 + g*8 + tid;   gg = gq[g*8 + tid];  bb = bq[g*8 + tid]; }
        else if (tid < 16) { o = g*24 + (tid - 8);  gg = gkv[o];         bb = bkv[o]; }
        else               { o = g*24 + 8 + (tid - 16); gg = gkv[o];     bb = bkv[o]; }
        float a, sh; chan_affine(o, gg, bb, a, sh);
        pa_s[tid] = a; pb_s[tid] = sh;
    }
    __syncthreads();

    for (int i = tid; i < RELW*8; i += 256) {
        int d = i >> 3, c = i & 7;
        rq_t[i] = rel[c*RELW + d] * A1oA0;
        rk_t[i] = rel[(8 + c)*RELW + d] * A2;
    }
    for (int i = tid; i < RELW*16; i += 256) {
        int d = i >> 4, c = i & 15;
        rv_t[i] = rel[(16 + c)*RELW + d] * vsve;
    }
#pragma unroll
    for (int it = 0; it < 3; it++) {
        int idx = tid + it * 256;
        int row = idx >> 1, q = idx & 1;
        int c = row / 48, i = row % 48;
        float4 vq = *(const float4*)(&g_Q [(g*384 + row) * B2304 + b0 + q*4]);
        float4 vk = *(const float4*)(&g_Kb[(g*384 + row) * B2304 + b0 + q*4]);
        float aq = pa_s[c] * A0, bqv = pb_s[c] * A0;   // fold A0 into Q
        float ak = pa_s[8 + c], bkv2 = pb_s[8 + c];
        float qv[4] = {vq.x, vq.y, vq.z, vq.w};
        float kv[4] = {vk.x, vk.y, vk.z, vk.w};
#pragma unroll
        for (int e = 0; e < 4; e++) {
            Qs[(q*4 + e)*384 + i*8 + c] = fmaf(aq, qv[e], bqv);
            Ks[(q*4 + e)*384 + i*8 + c] = fmaf(ak, kv[e], bkv2);
        }
    }
#pragma unroll
    for (int it = 0; it < 6; it++) {
        int idx = tid + it * 256;
        int row = idx >> 1, q = idx & 1;
        int c = row / 48, j = row % 48;
        float4 vv = *(const float4*)(&g_Vb[(g*768 + row) * B2304 + b0 + q*4]);
        float av = pa_s[16 + c] * vsv, bv = pb_s[16 + c] * vsv;
        float vf[4] = {vv.x, vv.y, vv.z, vv.w};
#pragma unroll
        for (int e = 0; e < 4; e++)
            Vs[(q*4 + e)*768 + j*16 + c] = fmaf(av, vf[e], bv);
    }
    for (int i = tid; i < 64; i += 256) red[i] = 0.0;
    __syncthreads();

    int ti = tid >> 4, tj = tid & 15;
    int i0 = ti * 3, j0 = tj * 3;
    int Dq = i0 - j0 + 47;     // rq row for (r,s): Dq + r - s
    int Dk = j0 - i0 + 47;     // rk row for (r,s): Dk + s - r

    int sv_i  = tid >> 2;
    int sv_c0 = (tid & 3) * 4;

    float lsv_s[4]  = {0,0,0,0}, lsv_q[4]  = {0,0,0,0};
    float lsve_s[4] = {0,0,0,0}, lsve_q[4] = {0,0,0,0};

    for (int bg = 0; bg < BTL; bg += 4) {
        // ---- logits + softmax for 4 bl into 4 sim buffers ----
#pragma unroll
        for (int h = 0; h < 4; h++) {
            int bl = bg + h;
            const float* Q = Qs + bl*384;
            const float* K = Ks + bl*384;
            float* sim = simA + h*48*SIMP;

            u64 k2[3][4];
#pragma unroll
            for (int s = 0; s < 3; s++) {
                ulonglong2 a = *(const ulonglong2*)(&K[(j0 + s)*8]);
                ulonglong2 b = *(const ulonglong2*)(&K[(j0 + s)*8 + 4]);
                k2[s][0] = a.x; k2[s][1] = a.y; k2[s][2] = b.x; k2[s][3] = b.y;
            }
            u64 acc[3][3];
#pragma unroll
            for (int r = 0; r < 3; r++)
#pragma unroll
                for (int s = 0; s < 3; s++) acc[r][s] = 0ull;

#pragma unroll
            for (int r = 0; r < 3; r++) {
                u64 q2[4];
                {
                    ulonglong2 a = *(const ulonglong2*)(&Q[(i0 + r)*8]);
                    ulonglong2 b = *(const ulonglong2*)(&Q[(i0 + r)*8 + 4]);
                    q2[0] = a.x; q2[1] = a.y; q2[2] = b.x; q2[3] = b.y;
                }
#pragma unroll
                for (int cp = 0; cp < 4; cp++)
#pragma unroll
                    for (int s = 0; s < 3; s++)
                        fma2(acc[r][s], q2[cp], k2[s][cp]);
#pragma unroll
                for (int s = 0; s < 3; s++) {
                    const float* rr = &rq_t[(Dq + r - s)*8];
                    ulonglong2 a = *(const ulonglong2*)(rr);
                    ulonglong2 b = *(const ulonglong2*)(rr + 4);
                    fma2(acc[r][s], q2[0], a.x); fma2(acc[r][s], q2[1], a.y);
                    fma2(acc[r][s], q2[2], b.x); fma2(acc[r][s], q2[3], b.y);
                }
            }
#pragma unroll
            for (int s = 0; s < 3; s++)
#pragma unroll
                for (int r = 0; r < 3; r++) {
                    const float* rr = &rk_t[(Dk + s - r)*8];
                    ulonglong2 a = *(const ulonglong2*)(rr);
                    ulonglong2 b = *(const ulonglong2*)(rr + 4);
                    fma2(acc[r][s], k2[s][0], a.x); fma2(acc[r][s], k2[s][1], a.y);
                    fma2(acc[r][s], k2[s][2], b.x); fma2(acc[r][s], k2[s][3], b.y);
                }

            float e[3][3], rs[3];
#pragma unroll
            for (int r = 0; r < 3; r++) {
                rs[r] = 0.f;
#pragma unroll
                for (int s = 0; s < 3; s++) {
                    float2 aa = unpk2(acc[r][s]);
                    e[r][s] = __expf(aa.x + aa.y + SH);
                    rs[r] += e[r][s];
                }
            }
#pragma unroll
            for (int off = 1; off < 16; off <<= 1) {
#pragma unroll
                for (int r = 0; r < 3; r++)
                    rs[r] += __shfl_xor_sync(0xffffffffu, rs[r], off);
            }
#pragma unroll
            for (int r = 0; r < 3; r++) {
                float rinv = 1.f / rs[r];
#pragma unroll
                for (int s = 0; s < 3; s++)
                    sim[(i0 + r)*SIMP + j0 + s] = e[r][s] * rinv;
            }
        }
        __syncthreads();

        // ---- sv / sve for 4 bl: rv load serves 4, sim read as float4 ----
        if (tid < 192) {
            u64 sv2[4][2], se2[4][2];
#pragma unroll
            for (int h = 0; h < 4; h++) {
                sv2[h][0] = 0ull; sv2[h][1] = 0ull;
                se2[h][0] = 0ull; se2[h][1] = 0ull;
            }
#pragma unroll 2
            for (int j0c = 0; j0c < 48; j0c += 4) {
                float4 s4[4];
#pragma unroll
                for (int h = 0; h < 4; h++)
                    s4[h] = *(const float4*)(&simA[h*48*SIMP + sv_i*SIMP + j0c]);
#pragma unroll
                for (int jj = 0; jj < 4; jj++) {
                    int j = j0c + jj;
                    ulonglong2 rv = *(const ulonglong2*)(&rv_t[(sv_i - j + 47)*16 + sv_c0]);
#pragma unroll
                    for (int h = 0; h < 4; h++) {
                        float sval = (jj == 0) ? s4[h].x : (jj == 1) ? s4[h].y
                                   : (jj == 2) ? s4[h].z : s4[h].w;
                        u64 s2 = bcast2(sval);
                        ulonglong2 v = *(const ulonglong2*)(&Vs[(bg + h)*768 + j*16 + sv_c0]);
                        fma2(sv2[h][0], s2, v.x);  fma2(sv2[h][1], s2, v.y);
                        fma2(se2[h][0], s2, rv.x); fma2(se2[h][1], s2, rv.y);
                    }
                }
            }
#pragma unroll
            for (int h = 0; h < 4; h++) {
                int b = b0 + bg + h;
                float* outv = &g_SV [b*6144 + g*768 + sv_c0*48 + sv_i];
                float* oute = &g_SVE[b*6144 + g*768 + sv_c0*48 + sv_i];
                float2 f0 = unpk2(sv2[h][0]), f1 = unpk2(sv2[h][1]);
                float2 g0 = unpk2(se2[h][0]), g1 = unpk2(se2[h][1]);
                float svv[4] = {f0.x, f0.y, f1.x, f1.y};
                float sev[4] = {g0.x, g0.y, g1.x, g1.y};
#pragma unroll
                for (int cc = 0; cc < 4; cc++) {
                    outv[cc*48] = svv[cc];
                    oute[cc*48] = sev[cc];
                    lsv_s[cc]  += svv[cc]; lsv_q[cc]  += svv[cc]*svv[cc];
                    lsve_s[cc] += sev[cc]; lsve_q[cc] += sev[cc]*sev[cc];
                }
            }
        }
        __syncthreads();
    }

    if (tid < 192) {
#pragma unroll
        for (int cc = 0; cc < 4; cc++) {
            int c = sv_c0 + cc;
            atomicAdd(&red[c*4+0], (double)lsv_s[cc]);
            atomicAdd(&red[c*4+1], (double)lsv_q[cc]);
            atomicAdd(&red[c*4+2], (double)lsve_s[cc]);
            atomicAdd(&red[c*4+3], (double)lsve_q[cc]);
        }
    }
    __syncthreads();
    if (tid < 16) {
        int o_sv  = (g*16 + tid)*2;
        int o_sve = o_sv + 1;
        atomicAdd(&g_outstats[o_sv*2+0],  red[tid*4+0]);
        atomicAdd(&g_outstats[o_sv*2+1],  red[tid*4+1]);
        atomicAdd(&g_outstats[o_sve*2+0], red[tid*4+2]);
        atomicAdd(&g_outstats[o_sve*2+1], red[tid*4+3]);
    }
}

// ---------------- out BN coefficients + restore accumulators to zero ----------------
__global__ void k_outco(const float* __restrict__ gout, const float* __restrict__ bout) {
    int o = threadIdx.x;
    double N = (double)P110592;
    double s1 = g_outstats[2*o], s2 = g_outstats[2*o+1];
    double mean = s1 / N, var = s2 / N - mean * mean;
    float inv = rsqrtf((float)var + EPS);
    float A = gout[o] * inv;
    g_oA[o] = A;
    g_oC[o] = bout[o] - A * (float)mean;
    g_outstats[2*o] = 0.0;  g_outstats[2*o+1] = 0.0;
    g_projstats[2*o] = 0.0; g_projstats[2*o+1] = 0.0;
    if (o < G8*2) ((double*)g_qkstat)[o] = 0.0;
}

// ---------------- final: affine-combine + transpose [b][r] -> [r][b] ----------------
__global__ __launch_bounds__(256)
void k_final(float* __restrict__ out) {
    __shared__ float tile[32][33];
    int r0 = blockIdx.x * 32;
    int b0 = blockIdx.y * 32;
    int tx = threadIdx.x, ty = threadIdx.y;

    int r = r0 + tx;
    int gc = r / 48;
    float Asv  = g_oA[gc*2],   Csv  = g_oC[gc*2];
    float Asve = g_oA[gc*2+1], Csve = g_oC[gc*2+1];
#pragma unroll
    for (int k = 0; k < 4; k++) {
        int b = b0 + ty + k*8;
        float v = Asv * g_SV[b*6144 + r] + Csv
                + Asve * g_SVE[b*6144 + r] + Csve;
        tile[ty + k*8][tx] = v;
    }
    __syncthreads();
#pragma unroll
    for (int k = 0; k < 4; k++) {
        int rr = r0 + ty + k*8;
        out[rr * B2304 + b0 + tx] = tile[tx][ty + k*8];
    }
}

// ---------------- launch ----------------
extern "C" void kernel_launch(void* const* d_in, const int* in_sizes, int n_in,
                              void* d_out, int out_size) {
    const float* x    = (const float*)d_in[0];
    const float* Wkv  = (const float*)d_in[1];
    const float* Wq   = (const float*)d_in[2];
    const float* gkv  = (const float*)d_in[3];
    const float* bkv  = (const float*)d_in[4];
    const float* gq   = (const float*)d_in[5];
    const float* bq   = (const float*)d_in[6];
    const float* gsim = (const float*)d_in[7];
    const float* bsim = (const float*)d_in[8];
    const float* gout = (const float*)d_in[9];
    const float* bout = (const float*)d_in[10];
    const float* rel  = (const float*)d_in[11];
    const float* fqr  = (const float*)d_in[12];
    const float* fkr  = (const float*)d_in[13];
    const float* fsv  = (const float*)d_in[14];
    const float* fsve = (const float*)d_in[15];
    float* out = (float*)d_out;

    cudaFuncSetAttribute(k_proj, cudaFuncAttributeMaxDynamicSharedMemorySize, PJ_SMEM);
    cudaFuncSetAttribute(k_attn, cudaFuncAttributeMaxDynamicSharedMemorySize, AT_SMEM);

    k_proj<<<dim3(P110592/128, 2), 256, PJ_SMEM>>>(x, Wkv, Wq);
    k_statsAB<<<dim3(48 + B2304/256, G8), 256>>>(gkv, bkv, gq, bq);
    k_simfin<<<1, 256>>>(rel, gsim, bsim, fqr, fkr);
    k_attn<<<dim3(B2304/BTL, G8), 256, AT_SMEM>>>(rel, fsv, fsve, gkv, bkv, gq, bq);
    k_outco<<<1, 256>>>(gout, bout);
    k_final<<<dim3(6144/32, B2304/32), dim3(32, 8)>>>(out);
}